// round 6
// baseline (speedup 1.0000x reference)
#include <cuda_runtime.h>
#include <math.h>
#include <stdint.h>

#define BB 8
#define NN 2048
#define FIN 512
#define FOUT 256
#define ALPHA 0.2f

// Scratch (allocation-free rule: __device__ globals)
__device__ float  g_Wh[BB * NN * FOUT];  // [b][j][n]
__device__ float  g_f1[BB * NN];
__device__ float  g_f2[BB * NN];
__device__ float2 g_e1[BB * NN];         // {exp(f1), exp(ALPHA*f1)}
__device__ float2 g_e2[BB * NN];         // {exp(f2), exp(ALPHA*f2)}

// ---------------------------------------------------------------------------
// mma.sync m16n8k8 tf32 helpers (legacy tensor path — PTX target-safe)
// ---------------------------------------------------------------------------
__device__ __forceinline__ void mma_tf32(float d[4], const uint32_t a[4],
                                         const uint32_t b[2]) {
    asm volatile(
        "mma.sync.aligned.m16n8k8.row.col.f32.tf32.tf32.f32 "
        "{%0,%1,%2,%3}, {%4,%5,%6,%7}, {%8,%9}, {%0,%1,%2,%3};"
        : "+f"(d[0]), "+f"(d[1]), "+f"(d[2]), "+f"(d[3])
        : "r"(a[0]), "r"(a[1]), "r"(a[2]), "r"(a[3]), "r"(b[0]), "r"(b[1]));
}
__device__ __forceinline__ uint32_t to_tf32(float x) {
    uint32_t r;
    asm("cvt.rna.tf32.f32 %0, %1;" : "=r"(r) : "f"(x));
    return r;
}
__device__ __forceinline__ float tf32f(float x) {
    return __uint_as_float(to_tf32(x));
}

// Pair layout: per row, 16 float2 slots; slot s = fk*4 + t holds k-pair
// (fk*8+t, fk*8+t+4). Row stride PR=20 float2 (4 pad). Consumer A-frag =
// 2x LDS.64, B-frag = 1x LDS.64, both conflict-free ((4g+t) mod 16 distinct).
#define PR 20

// Shared MMA consumer: acc += A_tile(128x32, rows at mw*32) * B_tile(256x32)^T
__device__ __forceinline__ void mma_tile(float acc[2][8][4], const float2* ap,
                                         const float2* bp, int mw, int nw,
                                         int g, int t) {
#pragma unroll
    for (int fk = 0; fk < 4; fk++) {
        uint32_t A[2][4];
#pragma unroll
        for (int fm = 0; fm < 2; fm++) {
            int row = mw * 32 + fm * 16 + g;
            float2 lo = ap[row * PR + fk * 4 + t];
            float2 hi = ap[(row + 8) * PR + fk * 4 + t];
            A[fm][0] = __float_as_uint(lo.x);
            A[fm][1] = __float_as_uint(hi.x);
            A[fm][2] = __float_as_uint(lo.y);
            A[fm][3] = __float_as_uint(hi.y);
        }
#pragma unroll
        for (int fn = 0; fn < 8; fn++) {
            int n = nw * 64 + fn * 8 + g;
            float2 bv = bp[n * PR + fk * 4 + t];
            uint32_t Bf[2] = {__float_as_uint(bv.x), __float_as_uint(bv.y)};
            mma_tf32(acc[0][fn], A[0], Bf);
            mma_tf32(acc[1][fn], A[1], Bf);
        }
    }
}

// ---------------------------------------------------------------------------
// Kernel 1: Wh = h @ W (tf32 mma.sync), pipelined ping-pong, LDS.64 frags.
// Block 512 thr, tile 128m x 256n, 16 k-tiles of 32. Grid 128 = 1 wave.
// ---------------------------------------------------------------------------
#define WG_AP 0                        // 2 * 128*20 float2 = 10240 floats
#define WG_BP 10240                    // 2 * 256*20 float2 = 20480 floats
#define WG_SMEM_F 30720                // 122880 B

__global__ __launch_bounds__(512, 1) void wh_tc(const float* __restrict__ h,
                                                const float* __restrict__ W) {
    extern __shared__ float sm[];
    float2* ap2 = (float2*)(sm + WG_AP);
    float2* bp2 = (float2*)(sm + WG_BP);

    const int tid  = threadIdx.x;
    const int warp = tid >> 5;
    const int lane = tid & 31;
    const int mw   = warp >> 2;
    const int nw   = warp & 3;
    const int g    = lane >> 2;
    const int t    = lane & 3;
    const int row0 = blockIdx.x * 128;

    // A-fill mapping: row r, k-pairs (q*8+c, q*8+c+4) -> slots q*4+c
    const int r = tid >> 2, q = tid & 3;
    // B-fill mapping: (fk,t) from low 4 bits -> k row kk = fk*8+t; n40 = tid>>4
    const int k4  = tid & 15;
    const int fkp = k4 >> 2;
    const int tp  = k4 & 3;
    const int kk  = fkp * 8 + tp;
    const int n40 = tid >> 4;  // + 32*p

    float acc[2][8][4];
#pragma unroll
    for (int fm = 0; fm < 2; fm++)
#pragma unroll
        for (int fn = 0; fn < 8; fn++)
#pragma unroll
            for (int c = 0; c < 4; c++) acc[fm][fn][c] = 0.f;

    float4 av0, av1;            // A regs (h row: k..k+3, k+4..k+7)
    float4 bv0[2], bv1[2];      // B regs (W rows kk, kk+4)

    // --- preload tile 0 ---
    {
        const float* asrc = h + (size_t)(row0 + r) * FIN + q * 8;
        av0 = *(const float4*)asrc;
        av1 = *(const float4*)(asrc + 4);
#pragma unroll
        for (int p = 0; p < 2; p++) {
            const float* bsrc = W + (size_t)kk * FOUT + (n40 + 32 * p) * 4;
            bv0[p] = *(const float4*)bsrc;
            bv1[p] = *(const float4*)(bsrc + 4 * FOUT);
        }
    }

    for (int kt = 0; kt < 16; kt++) {
        const int cur = kt & 1;
        // --- STS current tile regs into buffer cur ---
        {
            float2* ad = ap2 + cur * (128 * PR) + r * PR + q * 4;
            ad[0] = make_float2(tf32f(av0.x), tf32f(av1.x));
            ad[1] = make_float2(tf32f(av0.y), tf32f(av1.y));
            ad[2] = make_float2(tf32f(av0.z), tf32f(av1.z));
            ad[3] = make_float2(tf32f(av0.w), tf32f(av1.w));
#pragma unroll
            for (int p = 0; p < 2; p++) {
                float2* bd = bp2 + cur * (256 * PR) + fkp * 4 + tp;
                int nb = (n40 + 32 * p) * 4;
                float fx[4] = {bv0[p].x, bv0[p].y, bv0[p].z, bv0[p].w};
                float fy[4] = {bv1[p].x, bv1[p].y, bv1[p].z, bv1[p].w};
#pragma unroll
                for (int c = 0; c < 4; c++)
                    bd[(nb + c) * PR] = make_float2(tf32f(fx[c]), tf32f(fy[c]));
            }
        }
        // --- issue LDGs for tile kt+1 (land under this tile's MMA) ---
        if (kt < 15) {
            const int k0 = (kt + 1) * 32;
            const float* asrc = h + (size_t)(row0 + r) * FIN + k0 + q * 8;
            av0 = *(const float4*)asrc;
            av1 = *(const float4*)(asrc + 4);
#pragma unroll
            for (int p = 0; p < 2; p++) {
                const float* bsrc = W + (size_t)(k0 + kk) * FOUT + (n40 + 32 * p) * 4;
                bv0[p] = *(const float4*)bsrc;
                bv1[p] = *(const float4*)(bsrc + 4 * FOUT);
            }
        }
        __syncthreads();
        // --- MMA on buffer cur ---
        mma_tile(acc, ap2 + cur * (128 * PR), bp2 + cur * (256 * PR), mw, nw, g, t);
        __syncthreads();
    }

#pragma unroll
    for (int fm = 0; fm < 2; fm++) {
        int rr = row0 + mw * 32 + fm * 16 + g;
        float* o0 = g_Wh + (size_t)rr * FOUT;
        float* o1 = g_Wh + (size_t)(rr + 8) * FOUT;
#pragma unroll
        for (int fn = 0; fn < 8; fn++) {
            int col = nw * 64 + fn * 8 + t * 2;
            *(float2*)&o0[col] = make_float2(acc[fm][fn][0], acc[fm][fn][1]);
            *(float2*)&o1[col] = make_float2(acc[fm][fn][2], acc[fm][fn][3]);
        }
    }
}

// ---------------------------------------------------------------------------
// Kernel 2: f1/f2 + exp tables
// ---------------------------------------------------------------------------
__global__ __launch_bounds__(256) void f_kernel(const float* __restrict__ a) {
    int gwarp = (blockIdx.x * blockDim.x + threadIdx.x) >> 5;
    int lane  = threadIdx.x & 31;
    if (gwarp >= BB * NN) return;
    const float* wh = &g_Wh[(size_t)gwarp * FOUT];
    float s1 = 0.f, s2 = 0.f;
#pragma unroll
    for (int u = 0; u < 8; u++) {
        float v = wh[lane + 32 * u];
        s1 += v * a[lane + 32 * u];
        s2 += v * a[FOUT + lane + 32 * u];
    }
#pragma unroll
    for (int off = 16; off; off >>= 1) {
        s1 += __shfl_xor_sync(0xFFFFFFFFu, s1, off);
        s2 += __shfl_xor_sync(0xFFFFFFFFu, s2, off);
    }
    if (lane == 0) {
        g_f1[gwarp] = s1;
        g_f2[gwarp] = s2;
        g_e1[gwarp] = make_float2(__expf(s1), __expf(ALPHA * s1));
        g_e2[gwarp] = make_float2(__expf(s2), __expf(ALPHA * s2));
    }
}

// ---------------------------------------------------------------------------
// Kernel 3: fused masked-softmax aggregation; pipelined ping-pong + LDS.64.
// Block 512 thr, out tile 128 x 256, 64 j-tiles of 32. Grid 16x8 = 1 wave.
// ---------------------------------------------------------------------------
#define SM_WHP 0                       // 2 * 256*20 float2 = 20480 floats
#define SM_WP  20480                   // 2 * 128*20 float2 = 10240 floats
#define SM_F2  30720                   // 2048
#define SM_E2  32768                   // 4096
#define SM_F1  36864                   // 128
#define SM_DEN 36992                   // 128
#define ATTN_SMEM_F 37120              // 148480 B

__global__ __launch_bounds__(512, 1) void attn_mma(const int* __restrict__ adj,
                                                   float* __restrict__ out) {
    extern __shared__ float smem[];
    float2* whp2 = (float2*)(smem + SM_WHP);
    float2* wp2  = (float2*)(smem + SM_WP);
    float*  f2s  = smem + SM_F2;
    float2* e2s  = (float2*)(smem + SM_E2);
    float*  f1s  = smem + SM_F1;
    float*  dens = smem + SM_DEN;

    const int tid  = threadIdx.x;
    const int warp = tid >> 5;
    const int lane = tid & 31;
    const int mw   = warp >> 2;
    const int nw   = warp & 3;
    const int g    = lane >> 2;
    const int t    = lane & 3;
    const int b    = blockIdx.y;
    const int i0   = blockIdx.x * 128;

    // Stage f2 / e2 (full row) and f1 (tile)
    {
        const float4* f2g = (const float4*)(g_f2 + b * NN);
        ((float4*)f2s)[tid] = f2g[tid];
        const float4* e2g = (const float4*)(g_e2 + b * NN);
        ((float4*)e2s)[tid]       = e2g[tid];
        ((float4*)e2s)[tid + 512] = e2g[tid + 512];
        if (tid < 128) f1s[tid] = g_f1[b * NN + i0 + tid];
    }

    // w-fill: row r, j-pairs (jq*8+c, jq*8+c+4) -> slots jq*4+c.
    const int    r    = tid >> 2;
    const int    jq   = tid & 3;
    const int    k4   = tid & 15;
    const int    fkp  = k4 >> 2;
    const int    tp   = k4 & 3;
    const int    kk   = fkp * 8 + tp;
    const int    n40  = tid >> 4;
    const int4*  arow = (const int4*)(adj + ((size_t)(b * NN + i0 + r)) * NN + jq * 8);
    const float2 e1   = g_e1[b * NN + i0 + r];
    const float* whsrc = g_Wh + (size_t)b * NN * FOUT;

    float acc[2][8][4];
#pragma unroll
    for (int fm = 0; fm < 2; fm++)
#pragma unroll
        for (int fn = 0; fn < 8; fn++)
#pragma unroll
            for (int c = 0; c < 4; c++) acc[fm][fn][c] = 0.f;

    __syncthreads();
    const float f1v = f1s[r];
    float den = 0.f;

    int4   avA = arow[0], avB = arow[1];   // adj tile 0
    float4 wv0[2], wv1[2];                 // Wh regs (rows kk, kk+4)
    // preload Wh tile 0
#pragma unroll
    for (int p = 0; p < 2; p++) {
        const float* s = whsrc + (size_t)kk * FOUT + (n40 + 32 * p) * 4;
        wv0[p] = *(const float4*)s;
        wv1[p] = *(const float4*)(s + 4 * FOUT);
    }

    for (int tt = 0; tt < 64; tt++) {
        const int cur = tt & 1;
        const int j0  = tt * 32;
        // --- STS current tile (w from avA/avB + f2 sign; Wh from regs) ---
        {
            int am[8] = {avA.x, avA.y, avA.z, avA.w, avB.x, avB.y, avB.z, avB.w};
            const float*  f2p = f2s + j0 + jq * 8;
            const float2* e2p = e2s + j0 + jq * 8;
            float wv[8];
#pragma unroll
            for (int u = 0; u < 8; u++) {
                float  e  = f1v + f2p[u];
                float2 e2 = e2p[u];
                float  w  = (e > 0.f) ? e1.x * e2.x : e1.y * e2.y;
                w = (am[u] > 0) ? w : 0.f;
                wv[u] = tf32f(w);
                den += wv[u];
            }
            float2* wd = wp2 + cur * (128 * PR) + r * PR + jq * 4;
            wd[0] = make_float2(wv[0], wv[4]);
            wd[1] = make_float2(wv[1], wv[5]);
            wd[2] = make_float2(wv[2], wv[6]);
            wd[3] = make_float2(wv[3], wv[7]);
#pragma unroll
            for (int p = 0; p < 2; p++) {
                float2* bd = whp2 + cur * (256 * PR) + fkp * 4 + tp;
                int nb = (n40 + 32 * p) * 4;
                float fx[4] = {wv0[p].x, wv0[p].y, wv0[p].z, wv0[p].w};
                float fy[4] = {wv1[p].x, wv1[p].y, wv1[p].z, wv1[p].w};
#pragma unroll
                for (int c = 0; c < 4; c++)
                    bd[(nb + c) * PR] = make_float2(tf32f(fx[c]), tf32f(fy[c]));
            }
        }
        // --- issue LDGs for tile tt+1 (land under this tile's MMA) ---
        if (tt < 63) {
            avA = arow[(tt + 1) * 8];
            avB = arow[(tt + 1) * 8 + 1];
            const int jn = (tt + 1) * 32;
#pragma unroll
            for (int p = 0; p < 2; p++) {
                const float* s = whsrc + (size_t)(jn + kk) * FOUT + (n40 + 32 * p) * 4;
                wv0[p] = *(const float4*)s;
                wv1[p] = *(const float4*)(s + 4 * FOUT);
            }
        }
        __syncthreads();
        // --- MMA on buffer cur ---
        mma_tile(acc, wp2 + cur * (128 * PR), whp2 + cur * (256 * PR), mw, nw, g, t);
        __syncthreads();
    }

    // --- denominator: reduce 4 threads per row ---
    den += __shfl_xor_sync(0xFFFFFFFFu, den, 1);
    den += __shfl_xor_sync(0xFFFFFFFFu, den, 2);
    if (jq == 0) dens[r] = den;
    __syncthreads();

    // --- epilogue: /den, ELU, store ---
#pragma unroll
    for (int fm = 0; fm < 2; fm++) {
        int row0 = mw * 32 + fm * 16 + g;
        float inv0 = 1.f / dens[row0];
        float inv1 = 1.f / dens[row0 + 8];
        float* o0 = out + ((size_t)(b * NN + i0 + row0)) * FOUT;
        float* o1 = out + ((size_t)(b * NN + i0 + row0 + 8)) * FOUT;
#pragma unroll
        for (int fn = 0; fn < 8; fn++) {
            int col = nw * 64 + fn * 8 + t * 2;
            float x0 = acc[fm][fn][0] * inv0;
            float x1 = acc[fm][fn][1] * inv0;
            float x2 = acc[fm][fn][2] * inv1;
            float x3 = acc[fm][fn][3] * inv1;
            float2 v0, v1;
            v0.x = x0 > 0.f ? x0 : expm1f(x0);
            v0.y = x1 > 0.f ? x1 : expm1f(x1);
            v1.x = x2 > 0.f ? x2 : expm1f(x2);
            v1.y = x3 > 0.f ? x3 : expm1f(x3);
            *(float2*)&o0[col] = v0;
            *(float2*)&o1[col] = v1;
        }
    }
}

// ---------------------------------------------------------------------------
extern "C" void kernel_launch(void* const* d_in, const int* in_sizes, int n_in,
                              void* d_out, int out_size) {
    const float* h   = (const float*)d_in[0];
    const int*   adj = (const int*)d_in[1];
    const float* W   = (const float*)d_in[2];
    const float* a   = (const float*)d_in[3];
    float*       out = (float*)d_out;

    cudaFuncSetAttribute(wh_tc, cudaFuncAttributeMaxDynamicSharedMemorySize,
                         WG_SMEM_F * 4);
    cudaFuncSetAttribute(attn_mma, cudaFuncAttributeMaxDynamicSharedMemorySize,
                         ATTN_SMEM_F * 4);

    wh_tc<<<(BB * NN) / 128, 512, WG_SMEM_F * 4>>>(h, W);
    f_kernel<<<(BB * NN) / 8, 256>>>(a);
    attn_mma<<<dim3(NN / 128, BB), 512, ATTN_SMEM_F * 4>>>(adj, out);
}

// round 7
// speedup vs baseline: 1.1105x; 1.1105x over previous
#include <cuda_runtime.h>
#include <math.h>
#include <stdint.h>

#define BB 8
#define NN 2048
#define FIN 512
#define FOUT 256
#define ALPHA 0.2f

// Scratch (allocation-free rule: __device__ globals)
__device__ float  g_Wh[BB * NN * FOUT];  // [b][j][n]
__device__ float  g_f1[BB * NN];
__device__ float  g_f2[BB * NN];
__device__ float2 g_e1[BB * NN];         // {exp(f1), exp(ALPHA*f1)}
__device__ float2 g_e2[BB * NN];         // {exp(f2), exp(ALPHA*f2)}

// ---------------------------------------------------------------------------
// mma.sync m16n8k8 tf32 helpers (legacy tensor path — PTX target-safe)
// ---------------------------------------------------------------------------
__device__ __forceinline__ void mma_tf32(float d[4], const uint32_t a[4],
                                         const uint32_t b[2]) {
    asm volatile(
        "mma.sync.aligned.m16n8k8.row.col.f32.tf32.tf32.f32 "
        "{%0,%1,%2,%3}, {%4,%5,%6,%7}, {%8,%9}, {%0,%1,%2,%3};"
        : "+f"(d[0]), "+f"(d[1]), "+f"(d[2]), "+f"(d[3])
        : "r"(a[0]), "r"(a[1]), "r"(a[2]), "r"(a[3]), "r"(b[0]), "r"(b[1]));
}
__device__ __forceinline__ uint32_t to_tf32(float x) {
    uint32_t r;
    asm("cvt.rna.tf32.f32 %0, %1;" : "=r"(r) : "f"(x));
    return r;
}
__device__ __forceinline__ float tf32f(float x) {
    return __uint_as_float(to_tf32(x));
}

// ---------------------------------------------------------------------------
// Kernel 1: Wh = h @ W (tf32 mma.sync). Block 256 thr (8 warps, 2m x 4n),
// out tile 64m x 256n, 16 k-tiles of 32. Grid 256 -> occ 2 blocks/SM.
// ---------------------------------------------------------------------------
#define WG_AS 0                        // A_s [64][36]  = 2304 floats
#define WG_BS 2304                     // B_s [32][264] = 8448 floats
#define WG_SMEM_F 10752                // 43008 B

__global__ __launch_bounds__(256, 2) void wh_tc(const float* __restrict__ h,
                                                const float* __restrict__ W) {
    extern __shared__ float sm[];
    float* A_s = sm + WG_AS;
    float* B_s = sm + WG_BS;

    const int tid  = threadIdx.x;
    const int warp = tid >> 5;
    const int lane = tid & 31;
    const int mw   = warp >> 2;    // 0..1
    const int nw   = warp & 3;     // 0..3
    const int g    = lane >> 2;
    const int t    = lane & 3;
    const int row0 = blockIdx.x * 64;

    float acc[2][8][4];
#pragma unroll
    for (int fm = 0; fm < 2; fm++)
#pragma unroll
        for (int fn = 0; fn < 8; fn++)
#pragma unroll
            for (int c = 0; c < 4; c++) acc[fm][fn][c] = 0.f;

    const int r = tid >> 2, q = tid & 3;   // A-fill: row r (0..63), k-cols q*8

    for (int k0 = 0; k0 < FIN; k0 += 32) {
        // --- A tile: h[row0..+64][k0..+32], tf32-rounded ---
        {
            const float* src = h + (size_t)(row0 + r) * FIN + k0 + q * 8;
            float4 v0 = *(const float4*)src;
            float4 v1 = *(const float4*)(src + 4);
            float* dst = A_s + r * 36 + q * 8;
            dst[0] = tf32f(v0.x); dst[1] = tf32f(v0.y);
            dst[2] = tf32f(v0.z); dst[3] = tf32f(v0.w);
            dst[4] = tf32f(v1.x); dst[5] = tf32f(v1.y);
            dst[6] = tf32f(v1.z); dst[7] = tf32f(v1.w);
        }
        // --- B tile: W[k0..+32][0..256], tf32-rounded, stride 264 ---
#pragma unroll
        for (int p = 0; p < 8; p++) {
            int idx = tid + 256 * p;
            int row = idx >> 6, c4 = idx & 63;
            float4 v = *(const float4*)&W[(size_t)(k0 + row) * FOUT + c4 * 4];
            float4 o;
            o.x = tf32f(v.x); o.y = tf32f(v.y);
            o.z = tf32f(v.z); o.w = tf32f(v.w);
            *(float4*)&B_s[row * 264 + c4 * 4] = o;
        }
        __syncthreads();

#pragma unroll
        for (int fk = 0; fk < 4; fk++) {
            uint32_t A[2][4];
#pragma unroll
            for (int fm = 0; fm < 2; fm++) {
                const float* wa = A_s + (mw * 32 + fm * 16 + g) * 36 + fk * 8 + t;
                A[fm][0] = __float_as_uint(wa[0]);
                A[fm][1] = __float_as_uint(wa[8 * 36]);
                A[fm][2] = __float_as_uint(wa[4]);
                A[fm][3] = __float_as_uint(wa[8 * 36 + 4]);
            }
#pragma unroll
            for (int fn = 0; fn < 8; fn++) {
                uint32_t Bf[2];
                const float* wb = B_s + (fk * 8 + t) * 264 + nw * 64 + fn * 8 + g;
                Bf[0] = __float_as_uint(wb[0]);
                Bf[1] = __float_as_uint(wb[4 * 264]);
                mma_tf32(acc[0][fn], A[0], Bf);
                mma_tf32(acc[1][fn], A[1], Bf);
            }
        }
        __syncthreads();
    }

#pragma unroll
    for (int fm = 0; fm < 2; fm++) {
        int rr = row0 + mw * 32 + fm * 16 + g;
        float* o0 = g_Wh + (size_t)rr * FOUT;
        float* o1 = g_Wh + (size_t)(rr + 8) * FOUT;
#pragma unroll
        for (int fn = 0; fn < 8; fn++) {
            int col = nw * 64 + fn * 8 + t * 2;
            *(float2*)&o0[col] = make_float2(acc[fm][fn][0], acc[fm][fn][1]);
            *(float2*)&o1[col] = make_float2(acc[fm][fn][2], acc[fm][fn][3]);
        }
    }
}

// ---------------------------------------------------------------------------
// Kernel 2: f1/f2 + exp tables
// ---------------------------------------------------------------------------
__global__ __launch_bounds__(256) void f_kernel(const float* __restrict__ a) {
    int gwarp = (blockIdx.x * blockDim.x + threadIdx.x) >> 5;
    int lane  = threadIdx.x & 31;
    if (gwarp >= BB * NN) return;
    const float* wh = &g_Wh[(size_t)gwarp * FOUT];
    float s1 = 0.f, s2 = 0.f;
#pragma unroll
    for (int u = 0; u < 8; u++) {
        float v = wh[lane + 32 * u];
        s1 += v * a[lane + 32 * u];
        s2 += v * a[FOUT + lane + 32 * u];
    }
#pragma unroll
    for (int off = 16; off; off >>= 1) {
        s1 += __shfl_xor_sync(0xFFFFFFFFu, s1, off);
        s2 += __shfl_xor_sync(0xFFFFFFFFu, s2, off);
    }
    if (lane == 0) {
        g_f1[gwarp] = s1;
        g_f2[gwarp] = s2;
        g_e1[gwarp] = make_float2(__expf(s1), __expf(ALPHA * s1));
        g_e2[gwarp] = make_float2(__expf(s2), __expf(ALPHA * s2));
    }
}

// ---------------------------------------------------------------------------
// Kernel 3: fused masked-softmax aggregation (tf32 mma.sync, exp-free w-fill).
// Block 256 thr (8 warps, 2m x 4n), out tile 64 x 256, 64 j-tiles of 32.
// Grid 32x8 = 256 -> occ 2 blocks/SM (cross-block fill/MMA overlap).
// ---------------------------------------------------------------------------
#define SM_WH   0                      // 32*264 = 8448
#define SM_W    8448                   // 64*36  = 2304
#define SM_F2   10752                  // 2048
#define SM_E2   12800                  // float2[2048] = 4096
#define SM_F1   16896                  // 64
#define SM_DEN  16960                  // 64
#define ATTN_SMEM_F 17024              // 68096 B

__global__ __launch_bounds__(256, 2) void attn_mma(const int* __restrict__ adj,
                                                   float* __restrict__ out) {
    extern __shared__ float smem[];
    float*  Wh_s = smem + SM_WH;
    float*  w_s  = smem + SM_W;
    float*  f2s  = smem + SM_F2;
    float2* e2s  = (float2*)(smem + SM_E2);
    float*  f1s  = smem + SM_F1;
    float*  dens = smem + SM_DEN;

    const int tid  = threadIdx.x;
    const int warp = tid >> 5;
    const int lane = tid & 31;
    const int mw   = warp >> 2;    // 0..1
    const int nw   = warp & 3;     // 0..3
    const int g    = lane >> 2;
    const int t    = lane & 3;
    const int b    = blockIdx.y;
    const int i0   = blockIdx.x * 64;

    // Stage f2 / e2 (full row) and f1 (this 64-row tile)
    {
        const float4* f2g = (const float4*)(g_f2 + b * NN);
        ((float4*)f2s)[tid]       = f2g[tid];
        ((float4*)f2s)[tid + 256] = f2g[tid + 256];
        const float4* e2g = (const float4*)(g_e2 + b * NN);
#pragma unroll
        for (int p = 0; p < 4; p++)
            ((float4*)e2s)[tid + 256 * p] = e2g[tid + 256 * p];
        if (tid < 64) f1s[tid] = g_f1[b * NN + i0 + tid];
    }

    const int    r    = tid >> 2;   // i-row this thread fills (0..63)
    const int    jq   = tid & 3;    // 8 consecutive j at jq*8
    const int4*  arow = (const int4*)(adj + ((size_t)(b * NN + i0 + r)) * NN + jq * 8);
    const float2 e1   = g_e1[b * NN + i0 + r];
    const float* whsrc = g_Wh + (size_t)b * NN * FOUT;

    float acc[2][8][4];
#pragma unroll
    for (int fm = 0; fm < 2; fm++)
#pragma unroll
        for (int fn = 0; fn < 8; fn++)
#pragma unroll
            for (int c = 0; c < 4; c++) acc[fm][fn][c] = 0.f;

    __syncthreads();
    const float f1v = f1s[r];
    float den = 0.f;

    // adj prefetch for tile 0
    int4 avA = arow[0];
    int4 avB = arow[1];

    for (int tt = 0; tt < 64; tt++) {
        const int j0 = tt * 32;

        // --- w tile fill: exp-free, tf32-rounded (den uses identical values) ---
        {
            int am[8] = {avA.x, avA.y, avA.z, avA.w, avB.x, avB.y, avB.z, avB.w};
            float* wrow = w_s + r * 36 + jq * 8;
            const float*  f2p = f2s + j0 + jq * 8;
            const float2* e2p = e2s + j0 + jq * 8;
#pragma unroll
            for (int u = 0; u < 8; u++) {
                float  e  = f1v + f2p[u];
                float2 e2 = e2p[u];
                float  w  = (e > 0.f) ? e1.x * e2.x : e1.y * e2.y;
                w = (am[u] > 0) ? w : 0.f;
                float wv = tf32f(w);
                wrow[u] = wv;
                den += wv;
            }
        }
        // prefetch next tile's adj (lands under this tile's MMA phase)
        if (tt < 63) {
            avA = arow[(tt + 1) * 8];
            avB = arow[(tt + 1) * 8 + 1];
        }
        // --- Wh tile 32 x 256 (tf32-rounded), stride 264 ---
        {
            const float* src = whsrc + (size_t)j0 * FOUT;
#pragma unroll
            for (int p = 0; p < 8; p++) {
                int idx = tid + 256 * p;
                int row = idx >> 6, c4 = idx & 63;
                float4 v = *(const float4*)&src[(size_t)row * FOUT + c4 * 4];
                float4 o;
                o.x = tf32f(v.x); o.y = tf32f(v.y);
                o.z = tf32f(v.z); o.w = tf32f(v.w);
                *(float4*)&Wh_s[row * 264 + c4 * 4] = o;
            }
        }
        __syncthreads();

        // --- tensor-core tile: 4 k-frags of K=8 ---
#pragma unroll
        for (int fk = 0; fk < 4; fk++) {
            uint32_t A[2][4];
#pragma unroll
            for (int fm = 0; fm < 2; fm++) {
                const float* wa = w_s + (mw * 32 + fm * 16 + g) * 36 + fk * 8 + t;
                A[fm][0] = __float_as_uint(wa[0]);
                A[fm][1] = __float_as_uint(wa[8 * 36]);
                A[fm][2] = __float_as_uint(wa[4]);
                A[fm][3] = __float_as_uint(wa[8 * 36 + 4]);
            }
#pragma unroll
            for (int fn = 0; fn < 8; fn++) {
                uint32_t Bf[2];
                const float* wb = Wh_s + (fk * 8 + t) * 264 + nw * 64 + fn * 8 + g;
                Bf[0] = __float_as_uint(wb[0]);
                Bf[1] = __float_as_uint(wb[4 * 264]);
                mma_tf32(acc[0][fn], A[0], Bf);
                mma_tf32(acc[1][fn], A[1], Bf);
            }
        }
        __syncthreads();
    }

    // --- denominator: reduce 4 threads per row ---
    den += __shfl_xor_sync(0xFFFFFFFFu, den, 1);
    den += __shfl_xor_sync(0xFFFFFFFFu, den, 2);
    if (jq == 0) dens[r] = den;
    __syncthreads();

    // --- epilogue: /den, ELU, store ---
#pragma unroll
    for (int fm = 0; fm < 2; fm++) {
        int row0 = mw * 32 + fm * 16 + g;
        float inv0 = 1.f / dens[row0];
        float inv1 = 1.f / dens[row0 + 8];
        float* o0 = out + ((size_t)(b * NN + i0 + row0)) * FOUT;
        float* o1 = out + ((size_t)(b * NN + i0 + row0 + 8)) * FOUT;
#pragma unroll
        for (int fn = 0; fn < 8; fn++) {
            int col = nw * 64 + fn * 8 + t * 2;
            float x0 = acc[fm][fn][0] * inv0;
            float x1 = acc[fm][fn][1] * inv0;
            float x2 = acc[fm][fn][2] * inv1;
            float x3 = acc[fm][fn][3] * inv1;
            float2 v0, v1;
            v0.x = x0 > 0.f ? x0 : expm1f(x0);
            v0.y = x1 > 0.f ? x1 : expm1f(x1);
            v1.x = x2 > 0.f ? x2 : expm1f(x2);
            v1.y = x3 > 0.f ? x3 : expm1f(x3);
            *(float2*)&o0[col] = v0;
            *(float2*)&o1[col] = v1;
        }
    }
}

// ---------------------------------------------------------------------------
extern "C" void kernel_launch(void* const* d_in, const int* in_sizes, int n_in,
                              void* d_out, int out_size) {
    const float* h   = (const float*)d_in[0];
    const int*   adj = (const int*)d_in[1];
    const float* W   = (const float*)d_in[2];
    const float* a   = (const float*)d_in[3];
    float*       out = (float*)d_out;

    cudaFuncSetAttribute(wh_tc, cudaFuncAttributeMaxDynamicSharedMemorySize,
                         WG_SMEM_F * 4);
    cudaFuncSetAttribute(attn_mma, cudaFuncAttributeMaxDynamicSharedMemorySize,
                         ATTN_SMEM_F * 4);

    wh_tc<<<(BB * NN) / 64, 256, WG_SMEM_F * 4>>>(h, W);
    f_kernel<<<(BB * NN) / 8, 256>>>(a);
    attn_mma<<<dim3(NN / 64, BB), 256, ATTN_SMEM_F * 4>>>(adj, out);
}

// round 8
// speedup vs baseline: 1.2538x; 1.1290x over previous
#include <cuda_runtime.h>
#include <math.h>
#include <stdint.h>

#define BB 8
#define NN 2048
#define FIN 512
#define FOUT 256
#define ALPHA 0.2f

// Scratch (allocation-free rule: __device__ globals)
__device__ float  g_Wh[BB * NN * FOUT];  // [b][j][n]  (stored tf32-rounded)
__device__ float  g_f1[BB * NN];
__device__ float  g_f2[BB * NN];
__device__ float2 g_e1[BB * NN];         // {exp(f1), exp(ALPHA*f1)}
__device__ float2 g_e2[BB * NN];         // {exp(f2), exp(ALPHA*f2)}

// ---------------------------------------------------------------------------
// mma.sync m16n8k8 tf32 + cp.async helpers (all PTX target-safe, sm_80+)
// ---------------------------------------------------------------------------
__device__ __forceinline__ void mma_tf32(float d[4], const uint32_t a[4],
                                         const uint32_t b[2]) {
    asm volatile(
        "mma.sync.aligned.m16n8k8.row.col.f32.tf32.tf32.f32 "
        "{%0,%1,%2,%3}, {%4,%5,%6,%7}, {%8,%9}, {%0,%1,%2,%3};"
        : "+f"(d[0]), "+f"(d[1]), "+f"(d[2]), "+f"(d[3])
        : "r"(a[0]), "r"(a[1]), "r"(a[2]), "r"(a[3]), "r"(b[0]), "r"(b[1]));
}
__device__ __forceinline__ uint32_t to_tf32(float x) {
    uint32_t r;
    asm("cvt.rna.tf32.f32 %0, %1;" : "=r"(r) : "f"(x));
    return r;
}
__device__ __forceinline__ float tf32f(float x) {
    return __uint_as_float(to_tf32(x));
}
__device__ __forceinline__ void cp_async16(uint32_t dst_smem, const void* src) {
    asm volatile("cp.async.cg.shared.global [%0], [%1], 16;"
                 :: "r"(dst_smem), "l"(src));
}
#define CP_COMMIT() asm volatile("cp.async.commit_group;" ::: "memory")
#define CP_WAIT(n)  asm volatile("cp.async.wait_group %0;" :: "n"(n) : "memory")

// ---------------------------------------------------------------------------
// Kernel 1: Wh = h @ W (tf32 mma.sync). Block 256 thr (2m x 4n warps),
// out tile 64m x 256n. Epilogue stores g_Wh ALREADY tf32-rounded.
// ---------------------------------------------------------------------------
#define WG_AS 0                        // A_s [64][36]  = 2304 floats
#define WG_BS 2304                     // B_s [32][264] = 8448 floats
#define WG_SMEM_F 10752                // 43008 B

__global__ __launch_bounds__(256, 2) void wh_tc(const float* __restrict__ h,
                                                const float* __restrict__ W) {
    extern __shared__ float sm[];
    float* A_s = sm + WG_AS;
    float* B_s = sm + WG_BS;

    const int tid  = threadIdx.x;
    const int warp = tid >> 5;
    const int lane = tid & 31;
    const int mw   = warp >> 2;
    const int nw   = warp & 3;
    const int g    = lane >> 2;
    const int t    = lane & 3;
    const int row0 = blockIdx.x * 64;

    float acc[2][8][4];
#pragma unroll
    for (int fm = 0; fm < 2; fm++)
#pragma unroll
        for (int fn = 0; fn < 8; fn++)
#pragma unroll
            for (int c = 0; c < 4; c++) acc[fm][fn][c] = 0.f;

    const int r = tid >> 2, q = tid & 3;

    for (int k0 = 0; k0 < FIN; k0 += 32) {
        {
            const float* src = h + (size_t)(row0 + r) * FIN + k0 + q * 8;
            float4 v0 = *(const float4*)src;
            float4 v1 = *(const float4*)(src + 4);
            float* dst = A_s + r * 36 + q * 8;
            dst[0] = tf32f(v0.x); dst[1] = tf32f(v0.y);
            dst[2] = tf32f(v0.z); dst[3] = tf32f(v0.w);
            dst[4] = tf32f(v1.x); dst[5] = tf32f(v1.y);
            dst[6] = tf32f(v1.z); dst[7] = tf32f(v1.w);
        }
#pragma unroll
        for (int p = 0; p < 8; p++) {
            int idx = tid + 256 * p;
            int row = idx >> 6, c4 = idx & 63;
            float4 v = *(const float4*)&W[(size_t)(k0 + row) * FOUT + c4 * 4];
            float4 o;
            o.x = tf32f(v.x); o.y = tf32f(v.y);
            o.z = tf32f(v.z); o.w = tf32f(v.w);
            *(float4*)&B_s[row * 264 + c4 * 4] = o;
        }
        __syncthreads();

#pragma unroll
        for (int fk = 0; fk < 4; fk++) {
            uint32_t A[2][4];
#pragma unroll
            for (int fm = 0; fm < 2; fm++) {
                const float* wa = A_s + (mw * 32 + fm * 16 + g) * 36 + fk * 8 + t;
                A[fm][0] = __float_as_uint(wa[0]);
                A[fm][1] = __float_as_uint(wa[8 * 36]);
                A[fm][2] = __float_as_uint(wa[4]);
                A[fm][3] = __float_as_uint(wa[8 * 36 + 4]);
            }
#pragma unroll
            for (int fn = 0; fn < 8; fn++) {
                uint32_t Bf[2];
                const float* wb = B_s + (fk * 8 + t) * 264 + nw * 64 + fn * 8 + g;
                Bf[0] = __float_as_uint(wb[0]);
                Bf[1] = __float_as_uint(wb[4 * 264]);
                mma_tf32(acc[0][fn], A[0], Bf);
                mma_tf32(acc[1][fn], A[1], Bf);
            }
        }
        __syncthreads();
    }

    // Store tf32-rounded so attn can copy without cvt
#pragma unroll
    for (int fm = 0; fm < 2; fm++) {
        int rr = row0 + mw * 32 + fm * 16 + g;
        float* o0 = g_Wh + (size_t)rr * FOUT;
        float* o1 = g_Wh + (size_t)(rr + 8) * FOUT;
#pragma unroll
        for (int fn = 0; fn < 8; fn++) {
            int col = nw * 64 + fn * 8 + t * 2;
            *(float2*)&o0[col] = make_float2(tf32f(acc[fm][fn][0]), tf32f(acc[fm][fn][1]));
            *(float2*)&o1[col] = make_float2(tf32f(acc[fm][fn][2]), tf32f(acc[fm][fn][3]));
        }
    }
}

// ---------------------------------------------------------------------------
// Kernel 2: f1/f2 + exp tables (reads rounded Wh — negligible perturbation)
// ---------------------------------------------------------------------------
__global__ __launch_bounds__(256) void f_kernel(const float* __restrict__ a) {
    int gwarp = (blockIdx.x * blockDim.x + threadIdx.x) >> 5;
    int lane  = threadIdx.x & 31;
    if (gwarp >= BB * NN) return;
    const float* wh = &g_Wh[(size_t)gwarp * FOUT];
    float s1 = 0.f, s2 = 0.f;
#pragma unroll
    for (int u = 0; u < 8; u++) {
        float v = wh[lane + 32 * u];
        s1 += v * a[lane + 32 * u];
        s2 += v * a[FOUT + lane + 32 * u];
    }
#pragma unroll
    for (int off = 16; off; off >>= 1) {
        s1 += __shfl_xor_sync(0xFFFFFFFFu, s1, off);
        s2 += __shfl_xor_sync(0xFFFFFFFFu, s2, off);
    }
    if (lane == 0) {
        g_f1[gwarp] = s1;
        g_f2[gwarp] = s2;
        g_e1[gwarp] = make_float2(__expf(s1), __expf(ALPHA * s1));
        g_e2[gwarp] = make_float2(__expf(s2), __expf(ALPHA * s2));
    }
}

// ---------------------------------------------------------------------------
// Kernel 3: fused masked-softmax aggregation. R4 structure (128x256 tile,
// 512 thr) + cp.async double-buffered Wh tiles + double-buffered w tiles.
// Grid 16x8 = 128 blocks = single wave.
// ---------------------------------------------------------------------------
#define SM_WH0  0                      // 32*264 = 8448
#define SM_WH1  8448                   // 8448
#define SM_W0   16896                  // 128*36 = 4608
#define SM_W1   21504                  // 4608
#define SM_F2   26112                  // 2048
#define SM_E2   28160                  // 4096
#define SM_F1   32256                  // 128
#define SM_DEN  32384                  // 128
#define ATTN_SMEM_F 32512              // 130048 B

__global__ __launch_bounds__(512, 1) void attn_mma(const int* __restrict__ adj,
                                                   float* __restrict__ out) {
    extern __shared__ float smem[];
    float*  f2s  = smem + SM_F2;
    float2* e2s  = (float2*)(smem + SM_E2);
    float*  f1s  = smem + SM_F1;
    float*  dens = smem + SM_DEN;

    const int tid  = threadIdx.x;
    const int warp = tid >> 5;
    const int lane = tid & 31;
    const int mw   = warp >> 2;
    const int nw   = warp & 3;
    const int g    = lane >> 2;
    const int t    = lane & 3;
    const int b    = blockIdx.y;
    const int i0   = blockIdx.x * 128;

    // Stage f2 / e2 (full row) and f1 (tile)
    {
        const float4* f2g = (const float4*)(g_f2 + b * NN);
        ((float4*)f2s)[tid] = f2g[tid];
        const float4* e2g = (const float4*)(g_e2 + b * NN);
        ((float4*)e2s)[tid]       = e2g[tid];
        ((float4*)e2s)[tid + 512] = e2g[tid + 512];
        if (tid < 128) f1s[tid] = g_f1[b * NN + i0 + tid];
    }

    const int    r    = tid >> 2;   // i-row this thread fills (4 thr/row)
    const int    jq   = tid & 3;    // 8 consecutive j at jq*8
    const int4*  arow = (const int4*)(adj + ((size_t)(b * NN + i0 + r)) * NN + jq * 8);
    const float2 e1   = g_e1[b * NN + i0 + r];
    const float* whsrc = g_Wh + (size_t)b * NN * FOUT;

    // cp.async mapping: row = tid>>4 (0..31), seg = tid&15; 4 segs of 16B/row
    const int cprow = tid >> 4;
    const int cpseg = tid & 15;
    const uint32_t smem_base = (uint32_t)__cvta_generic_to_shared(smem);

    float acc[2][8][4];
#pragma unroll
    for (int fm = 0; fm < 2; fm++)
#pragma unroll
        for (int fn = 0; fn < 8; fn++)
#pragma unroll
            for (int c = 0; c < 4; c++) acc[fm][fn][c] = 0.f;

    // issue Wh tile 0 copy (group 0)
    {
        const float* src = whsrc + (size_t)cprow * FOUT + cpseg * 4;
        uint32_t dst = smem_base + (SM_WH0 + cprow * 264 + cpseg * 4) * 4;
#pragma unroll
        for (int p = 0; p < 4; p++)
            cp_async16(dst + p * 64 * 4, src + p * 64);
        CP_COMMIT();
    }

    __syncthreads();
    const float f1v = f1s[r];
    float den = 0.f;

    int4 avA = arow[0];
    int4 avB = arow[1];

    for (int tt = 0; tt < 64; tt++) {
        const int cur = tt & 1;
        const int j0  = tt * 32;

        // --- w tile fill into w_s[cur] (exp-free, tf32-rounded) ---
        {
            int am[8] = {avA.x, avA.y, avA.z, avA.w, avB.x, avB.y, avB.z, avB.w};
            const float*  f2p = f2s + j0 + jq * 8;
            const float2* e2p = e2s + j0 + jq * 8;
            float wv[8];
#pragma unroll
            for (int u = 0; u < 8; u++) {
                float  e  = f1v + f2p[u];
                float2 e2 = e2p[u];
                float  w  = (e > 0.f) ? e1.x * e2.x : e1.y * e2.y;
                w = (am[u] > 0) ? w : 0.f;
                wv[u] = tf32f(w);
                den += wv[u];
            }
            float* wrow = smem + (cur ? SM_W1 : SM_W0) + r * 36 + jq * 8;
            *(float4*)&wrow[0] = make_float4(wv[0], wv[1], wv[2], wv[3]);
            *(float4*)&wrow[4] = make_float4(wv[4], wv[5], wv[6], wv[7]);
        }
        // --- prefetch next adj + issue cp.async for Wh tile tt+1 ---
        if (tt < 63) {
            avA = arow[(tt + 1) * 8];
            avB = arow[(tt + 1) * 8 + 1];
            const float* src = whsrc + (size_t)((tt + 1) * 32 + cprow) * FOUT + cpseg * 4;
            uint32_t dst = smem_base +
                ((cur ? SM_WH0 : SM_WH1) + cprow * 264 + cpseg * 4) * 4;
#pragma unroll
            for (int p = 0; p < 4; p++)
                cp_async16(dst + p * 64 * 4, src + p * 64);
            CP_COMMIT();
            CP_WAIT(1);   // tile tt arrived; tile tt+1 in flight
        } else {
            CP_WAIT(0);
        }
        __syncthreads();

        // --- tensor-core tile on buffers [cur] ---
        const float* w_s  = smem + (cur ? SM_W1 : SM_W0);
        const float* Wh_s = smem + (cur ? SM_WH1 : SM_WH0);
#pragma unroll
        for (int fk = 0; fk < 4; fk++) {
            uint32_t A[2][4];
#pragma unroll
            for (int fm = 0; fm < 2; fm++) {
                const float* wa = w_s + (mw * 32 + fm * 16 + g) * 36 + fk * 8 + t;
                A[fm][0] = __float_as_uint(wa[0]);
                A[fm][1] = __float_as_uint(wa[8 * 36]);
                A[fm][2] = __float_as_uint(wa[4]);
                A[fm][3] = __float_as_uint(wa[8 * 36 + 4]);
            }
#pragma unroll
            for (int fn = 0; fn < 8; fn++) {
                uint32_t Bf[2];
                const float* wb = Wh_s + (fk * 8 + t) * 264 + nw * 64 + fn * 8 + g;
                Bf[0] = __float_as_uint(wb[0]);
                Bf[1] = __float_as_uint(wb[4 * 264]);
                mma_tf32(acc[0][fn], A[0], Bf);
                mma_tf32(acc[1][fn], A[1], Bf);
            }
        }
        __syncthreads();
    }

    // --- denominator: reduce 4 threads per row ---
    den += __shfl_xor_sync(0xFFFFFFFFu, den, 1);
    den += __shfl_xor_sync(0xFFFFFFFFu, den, 2);
    if (jq == 0) dens[r] = den;
    __syncthreads();

    // --- epilogue: /den, ELU, store ---
#pragma unroll
    for (int fm = 0; fm < 2; fm++) {
        int row0 = mw * 32 + fm * 16 + g;
        float inv0 = 1.f / dens[row0];
        float inv1 = 1.f / dens[row0 + 8];
        float* o0 = out + ((size_t)(b * NN + i0 + row0)) * FOUT;
        float* o1 = out + ((size_t)(b * NN + i0 + row0 + 8)) * FOUT;
#pragma unroll
        for (int fn = 0; fn < 8; fn++) {
            int col = nw * 64 + fn * 8 + t * 2;
            float x0 = acc[fm][fn][0] * inv0;
            float x1 = acc[fm][fn][1] * inv0;
            float x2 = acc[fm][fn][2] * inv1;
            float x3 = acc[fm][fn][3] * inv1;
            float2 v0, v1;
            v0.x = x0 > 0.f ? x0 : expm1f(x0);
            v0.y = x1 > 0.f ? x1 : expm1f(x1);
            v1.x = x2 > 0.f ? x2 : expm1f(x2);
            v1.y = x3 > 0.f ? x3 : expm1f(x3);
            *(float2*)&o0[col] = v0;
            *(float2*)&o1[col] = v1;
        }
    }
}

// ---------------------------------------------------------------------------
extern "C" void kernel_launch(void* const* d_in, const int* in_sizes, int n_in,
                              void* d_out, int out_size) {
    const float* h   = (const float*)d_in[0];
    const int*   adj = (const int*)d_in[1];
    const float* W   = (const float*)d_in[2];
    const float* a   = (const float*)d_in[3];
    float*       out = (float*)d_out;

    cudaFuncSetAttribute(wh_tc, cudaFuncAttributeMaxDynamicSharedMemorySize,
                         WG_SMEM_F * 4);
    cudaFuncSetAttribute(attn_mma, cudaFuncAttributeMaxDynamicSharedMemorySize,
                         ATTN_SMEM_F * 4);

    wh_tc<<<(BB * NN) / 64, 256, WG_SMEM_F * 4>>>(h, W);
    f_kernel<<<(BB * NN) / 8, 256>>>(a);
    attn_mma<<<dim3(NN / 128, BB), 512, ATTN_SMEM_F * 4>>>(adj, out);
}

// round 9
// speedup vs baseline: 1.3124x; 1.0467x over previous
#include <cuda_runtime.h>
#include <cuda_fp16.h>
#include <math.h>
#include <stdint.h>

#define BB 8
#define NN 2048
#define FIN 512
#define FOUT 256
#define ALPHA 0.2f

// Scratch (allocation-free rule: __device__ globals)
__device__ float    g_Wh[BB * NN * FOUT];   // [b][j][n] fp32 (tf32-rounded)
__device__ __half   g_WhT[BB * FOUT * NN];  // [b][n][j] fp16 (attn B operand)
__device__ float    g_f1[BB * NN];
__device__ float    g_f2[BB * NN];
__device__ float2   g_e1[BB * NN];          // {exp(f1), exp(ALPHA*f1)}
__device__ float2   g_e2[BB * NN];          // {exp(f2), exp(ALPHA*f2)}
__device__ unsigned g_m2bits[BB * 2];       // per-batch max of e2p / e2n (bits)

// ---------------------------------------------------------------------------
// mma.sync + cp.async helpers (sm_80 baseline — PTX target-safe)
// ---------------------------------------------------------------------------
__device__ __forceinline__ void mma_tf32(float d[4], const uint32_t a[4],
                                         const uint32_t b[2]) {
    asm volatile(
        "mma.sync.aligned.m16n8k8.row.col.f32.tf32.tf32.f32 "
        "{%0,%1,%2,%3}, {%4,%5,%6,%7}, {%8,%9}, {%0,%1,%2,%3};"
        : "+f"(d[0]), "+f"(d[1]), "+f"(d[2]), "+f"(d[3])
        : "r"(a[0]), "r"(a[1]), "r"(a[2]), "r"(a[3]), "r"(b[0]), "r"(b[1]));
}
__device__ __forceinline__ void mma_f16(float d[4], const uint32_t a[4],
                                        uint32_t b0, uint32_t b1) {
    asm volatile(
        "mma.sync.aligned.m16n8k16.row.col.f32.f16.f16.f32 "
        "{%0,%1,%2,%3}, {%4,%5,%6,%7}, {%8,%9}, {%0,%1,%2,%3};"
        : "+f"(d[0]), "+f"(d[1]), "+f"(d[2]), "+f"(d[3])
        : "r"(a[0]), "r"(a[1]), "r"(a[2]), "r"(a[3]), "r"(b0), "r"(b1));
}
__device__ __forceinline__ uint32_t to_tf32(float x) {
    uint32_t r;
    asm("cvt.rna.tf32.f32 %0, %1;" : "=r"(r) : "f"(x));
    return r;
}
__device__ __forceinline__ float tf32f(float x) {
    return __uint_as_float(to_tf32(x));
}
__device__ __forceinline__ void cp_async16(uint32_t dst_smem, const void* src) {
    asm volatile("cp.async.cg.shared.global [%0], [%1], 16;"
                 :: "r"(dst_smem), "l"(src));
}
#define CP_COMMIT() asm volatile("cp.async.commit_group;" ::: "memory")
#define CP_WAIT(n)  asm volatile("cp.async.wait_group %0;" :: "n"(n) : "memory")

// ---------------------------------------------------------------------------
// Kernel 1: Wh = h @ W (tf32 mma.sync). Block 256 thr (2m x 4n warps),
// out tile 64m x 256n. Stores g_Wh (fp32, tf32-rounded) and g_WhT (fp16).
// ---------------------------------------------------------------------------
#define WG_AS 0                        // A_s [64][36]  = 2304 floats
#define WG_BS 2304                     // B_s [32][264] = 8448 floats
#define WG_SMEM_F 10752                // 43008 B

__global__ __launch_bounds__(256, 2) void wh_tc(const float* __restrict__ h,
                                                const float* __restrict__ W) {
    extern __shared__ float sm[];
    float* A_s = sm + WG_AS;
    float* B_s = sm + WG_BS;

    const int tid  = threadIdx.x;
    const int warp = tid >> 5;
    const int lane = tid & 31;
    const int mw   = warp >> 2;
    const int nw   = warp & 3;
    const int g    = lane >> 2;
    const int t    = lane & 3;
    const int row0 = blockIdx.x * 64;

    float acc[2][8][4];
#pragma unroll
    for (int fm = 0; fm < 2; fm++)
#pragma unroll
        for (int fn = 0; fn < 8; fn++)
#pragma unroll
            for (int c = 0; c < 4; c++) acc[fm][fn][c] = 0.f;

    const int r = tid >> 2, q = tid & 3;

    for (int k0 = 0; k0 < FIN; k0 += 32) {
        {
            const float* src = h + (size_t)(row0 + r) * FIN + k0 + q * 8;
            float4 v0 = *(const float4*)src;
            float4 v1 = *(const float4*)(src + 4);
            float* dst = A_s + r * 36 + q * 8;
            dst[0] = tf32f(v0.x); dst[1] = tf32f(v0.y);
            dst[2] = tf32f(v0.z); dst[3] = tf32f(v0.w);
            dst[4] = tf32f(v1.x); dst[5] = tf32f(v1.y);
            dst[6] = tf32f(v1.z); dst[7] = tf32f(v1.w);
        }
#pragma unroll
        for (int p = 0; p < 8; p++) {
            int idx = tid + 256 * p;
            int row = idx >> 6, c4 = idx & 63;
            float4 v = *(const float4*)&W[(size_t)(k0 + row) * FOUT + c4 * 4];
            float4 o;
            o.x = tf32f(v.x); o.y = tf32f(v.y);
            o.z = tf32f(v.z); o.w = tf32f(v.w);
            *(float4*)&B_s[row * 264 + c4 * 4] = o;
        }
        __syncthreads();

#pragma unroll
        for (int fk = 0; fk < 4; fk++) {
            uint32_t A[2][4];
#pragma unroll
            for (int fm = 0; fm < 2; fm++) {
                const float* wa = A_s + (mw * 32 + fm * 16 + g) * 36 + fk * 8 + t;
                A[fm][0] = __float_as_uint(wa[0]);
                A[fm][1] = __float_as_uint(wa[8 * 36]);
                A[fm][2] = __float_as_uint(wa[4]);
                A[fm][3] = __float_as_uint(wa[8 * 36 + 4]);
            }
#pragma unroll
            for (int fn = 0; fn < 8; fn++) {
                uint32_t Bf[2];
                const float* wb = B_s + (fk * 8 + t) * 264 + nw * 64 + fn * 8 + g;
                Bf[0] = __float_as_uint(wb[0]);
                Bf[1] = __float_as_uint(wb[4 * 264]);
                mma_tf32(acc[0][fn], A[0], Bf);
                mma_tf32(acc[1][fn], A[1], Bf);
            }
        }
        __syncthreads();
    }

#pragma unroll
    for (int fm = 0; fm < 2; fm++) {
        int rr = row0 + mw * 32 + fm * 16 + g;
        int bb = rr >> 11;
        int jj = rr & (NN - 1);
        float* o0 = g_Wh + (size_t)rr * FOUT;
        float* o1 = g_Wh + (size_t)(rr + 8) * FOUT;
#pragma unroll
        for (int fn = 0; fn < 8; fn++) {
            int col = nw * 64 + fn * 8 + t * 2;
            // fp32 (tf32-rounded) row-major for f_kernel
            *(float2*)&o0[col] = make_float2(tf32f(acc[fm][fn][0]), tf32f(acc[fm][fn][1]));
            *(float2*)&o1[col] = make_float2(tf32f(acc[fm][fn][2]), tf32f(acc[fm][fn][3]));
            // fp16 transposed [b][n][j] for attn B operand
            size_t base = ((size_t)bb * FOUT + col) * NN + jj;
            g_WhT[base]          = __float2half_rn(acc[fm][fn][0]);
            g_WhT[base + NN]     = __float2half_rn(acc[fm][fn][1]);
            g_WhT[base + 8]      = __float2half_rn(acc[fm][fn][2]);
            g_WhT[base + NN + 8] = __float2half_rn(acc[fm][fn][3]);
        }
    }
}

// ---------------------------------------------------------------------------
// Kernel 2: f1/f2 + exp tables + per-batch max(e2p), max(e2n) via atomicMax
// (idempotent -> deterministic across graph replays; e2 > 0 so bit-max = max)
// ---------------------------------------------------------------------------
__global__ __launch_bounds__(256) void f_kernel(const float* __restrict__ a) {
    int gwarp = (blockIdx.x * blockDim.x + threadIdx.x) >> 5;
    int lane  = threadIdx.x & 31;
    if (gwarp >= BB * NN) return;
    const float* wh = &g_Wh[(size_t)gwarp * FOUT];
    float s1 = 0.f, s2 = 0.f;
#pragma unroll
    for (int u = 0; u < 8; u++) {
        float v = wh[lane + 32 * u];
        s1 += v * a[lane + 32 * u];
        s2 += v * a[FOUT + lane + 32 * u];
    }
#pragma unroll
    for (int off = 16; off; off >>= 1) {
        s1 += __shfl_xor_sync(0xFFFFFFFFu, s1, off);
        s2 += __shfl_xor_sync(0xFFFFFFFFu, s2, off);
    }
    if (lane == 0) {
        g_f1[gwarp] = s1;
        g_f2[gwarp] = s2;
        float e2p = __expf(s2), e2n = __expf(ALPHA * s2);
        g_e1[gwarp] = make_float2(__expf(s1), __expf(ALPHA * s1));
        g_e2[gwarp] = make_float2(e2p, e2n);
        int b = gwarp >> 11;
        atomicMax(&g_m2bits[b * 2 + 0], __float_as_uint(e2p));
        atomicMax(&g_m2bits[b * 2 + 1], __float_as_uint(e2n));
    }
}

// ---------------------------------------------------------------------------
// Kernel 3: fused masked-softmax aggregation, fp16 m16n8k16 mma (fp32 acc).
// Per-row scaling w/s_i (softmax-invariant) keeps fp16 in range [0,1].
// 512 thr, out tile 128 x 256, 64 j-tiles of 32; cp.async double-buffered
// fp16 WhT tiles (raw byte copy). Grid 16x8 = 128 = single wave.
// smem rows: 20 float-slots (= half2) per 32-k row -> conflict-free LDS.32.
// ---------------------------------------------------------------------------
#define SM_WH0  0                      // 256*20 = 5120 floats (half2 slots)
#define SM_WH1  5120
#define SM_W0   10240                  // 128*20 = 2560
#define SM_W1   12800
#define SM_F2   15360                  // 2048
#define SM_E2   17408                  // float2[2048] = 4096
#define SM_F1   21504                  // 128
#define SM_DEN  21632                  // 128
#define ATTN_SMEM_F 21760              // 87040 B

__global__ __launch_bounds__(512, 1) void attn_mma(const int* __restrict__ adj,
                                                   float* __restrict__ out) {
    extern __shared__ float smem[];
    float*  f2s  = smem + SM_F2;
    float2* e2s  = (float2*)(smem + SM_E2);
    float*  f1s  = smem + SM_F1;
    float*  dens = smem + SM_DEN;

    const int tid  = threadIdx.x;
    const int warp = tid >> 5;
    const int lane = tid & 31;
    const int mw   = warp >> 2;
    const int nw   = warp & 3;
    const int g    = lane >> 2;
    const int t    = lane & 3;
    const int b    = blockIdx.y;
    const int i0   = blockIdx.x * 128;

    // Stage f2 / e2 (full row) and f1 (tile)
    {
        const float4* f2g = (const float4*)(g_f2 + b * NN);
        ((float4*)f2s)[tid] = f2g[tid];
        const float4* e2g = (const float4*)(g_e2 + b * NN);
        ((float4*)e2s)[tid]       = e2g[tid];
        ((float4*)e2s)[tid + 512] = e2g[tid + 512];
        if (tid < 128) f1s[tid] = g_f1[b * NN + i0 + tid];
    }

    const int    r    = tid >> 2;   // i-row this thread fills (4 thr/row)
    const int    jq   = tid & 3;    // 8 consecutive j at jq*8
    const int4*  arow = (const int4*)(adj + ((size_t)(b * NN + i0 + r)) * NN + jq * 8);
    const float2 e1   = g_e1[b * NN + i0 + r];
    const __half* whTsrc = g_WhT + (size_t)b * FOUT * NN;

    // per-row scale: s_i = max(e1p*M2p, e1n*M2n)  (tight upper bound on w)
    const float M2p  = __uint_as_float(g_m2bits[b * 2 + 0]);
    const float M2n  = __uint_as_float(g_m2bits[b * 2 + 1]);
    const float sinv = 1.f / fmaxf(e1.x * M2p, e1.y * M2n);
    const float c1p  = e1.x * sinv;
    const float c1n  = e1.y * sinv;

    // cp.async mapping: n-row = tid>>2 (+128p), 16B chunk = tid&3
    const int cpn = tid >> 2;
    const int cpc = tid & 3;
    const uint32_t smem_base = (uint32_t)__cvta_generic_to_shared(smem);

    float acc[2][8][4];
#pragma unroll
    for (int fm = 0; fm < 2; fm++)
#pragma unroll
        for (int fn = 0; fn < 8; fn++)
#pragma unroll
            for (int c = 0; c < 4; c++) acc[fm][fn][c] = 0.f;

    // issue WhT tile 0 copy (rows n: 64B each = 4 chunks)
    {
#pragma unroll
        for (int p = 0; p < 2; p++) {
            int n = cpn + 128 * p;
            const __half* src = whTsrc + (size_t)n * NN + cpc * 8;
            uint32_t dst = smem_base + (SM_WH0 + n * 20 + cpc * 4) * 4;
            cp_async16(dst, src);
        }
        CP_COMMIT();
    }

    __syncthreads();
    const float f1v = f1s[r];
    float den = 0.f;

    int4 avA = arow[0];
    int4 avB = arow[1];

    for (int tt = 0; tt < 64; tt++) {
        const int cur = tt & 1;
        const int j0  = tt * 32;

        // --- w tile fill: exp-free, scaled, fp16-rounded (den matches) ---
        {
            int am[8] = {avA.x, avA.y, avA.z, avA.w, avB.x, avB.y, avB.z, avB.w};
            const float*  f2p = f2s + j0 + jq * 8;
            const float2* e2p = e2s + j0 + jq * 8;
            float wv[8];
#pragma unroll
            for (int u = 0; u < 8; u++) {
                float  e  = f1v + f2p[u];
                float2 e2 = e2p[u];
                float  w  = (e > 0.f) ? c1p * e2.x : c1n * e2.y;
                wv[u] = (am[u] > 0) ? w : 0.f;
            }
            uint32_t pk[4];
#pragma unroll
            for (int i = 0; i < 4; i++) {
                __half2 hp = __floats2half2_rn(wv[2 * i], wv[2 * i + 1]);
                pk[i] = *(uint32_t*)&hp;
                float2 hf = __half22float2(hp);
                den += hf.x + hf.y;
            }
            float* wd = smem + (cur ? SM_W1 : SM_W0) + r * 20 + jq * 4;
            *(float4*)wd = make_float4(__uint_as_float(pk[0]), __uint_as_float(pk[1]),
                                       __uint_as_float(pk[2]), __uint_as_float(pk[3]));
        }
        // --- prefetch next adj + cp.async for WhT tile tt+1 ---
        if (tt < 63) {
            avA = arow[(tt + 1) * 8];
            avB = arow[(tt + 1) * 8 + 1];
#pragma unroll
            for (int p = 0; p < 2; p++) {
                int n = cpn + 128 * p;
                const __half* src = whTsrc + (size_t)n * NN + (tt + 1) * 32 + cpc * 8;
                uint32_t dst = smem_base +
                    ((cur ? SM_WH0 : SM_WH1) + n * 20 + cpc * 4) * 4;
                cp_async16(dst, src);
            }
            CP_COMMIT();
            CP_WAIT(1);
        } else {
            CP_WAIT(0);
        }
        __syncthreads();

        // --- fp16 tensor tile: 2 k-frags of K=16 ---
        const float* w_s = smem + (cur ? SM_W1 : SM_W0);
        const float* B_s = smem + (cur ? SM_WH1 : SM_WH0);
#pragma unroll
        for (int fk = 0; fk < 2; fk++) {
            uint32_t A[2][4];
#pragma unroll
            for (int fm = 0; fm < 2; fm++) {
                const float* wa = w_s + (mw * 32 + fm * 16 + g) * 20 + fk * 8 + t;
                A[fm][0] = __float_as_uint(wa[0]);
                A[fm][1] = __float_as_uint(wa[160]);      // +8 rows
                A[fm][2] = __float_as_uint(wa[4]);
                A[fm][3] = __float_as_uint(wa[164]);
            }
#pragma unroll
            for (int fn = 0; fn < 8; fn++) {
                const float* wb = B_s + (nw * 64 + fn * 8 + g) * 20 + fk * 8 + t;
                uint32_t b0 = __float_as_uint(wb[0]);
                uint32_t b1 = __float_as_uint(wb[4]);
                mma_f16(acc[0][fn], A[0], b0, b1);
                mma_f16(acc[1][fn], A[1], b0, b1);
            }
        }
        __syncthreads();
    }

    // --- denominator: reduce 4 threads per row (scale cancels in ratio) ---
    den += __shfl_xor_sync(0xFFFFFFFFu, den, 1);
    den += __shfl_xor_sync(0xFFFFFFFFu, den, 2);
    if (jq == 0) dens[r] = den;
    __syncthreads();

    // --- epilogue: /den, ELU, store ---
#pragma unroll
    for (int fm = 0; fm < 2; fm++) {
        int row0 = mw * 32 + fm * 16 + g;
        float inv0 = 1.f / dens[row0];
        float inv1 = 1.f / dens[row0 + 8];
        float* o0 = out + ((size_t)(b * NN + i0 + row0)) * FOUT;
        float* o1 = out + ((size_t)(b * NN + i0 + row0 + 8)) * FOUT;
#pragma unroll
        for (int fn = 0; fn < 8; fn++) {
            int col = nw * 64 + fn * 8 + t * 2;
            float x0 = acc[fm][fn][0] * inv0;
            float x1 = acc[fm][fn][1] * inv0;
            float x2 = acc[fm][fn][2] * inv1;
            float x3 = acc[fm][fn][3] * inv1;
            float2 v0, v1;
            v0.x = x0 > 0.f ? x0 : expm1f(x0);
            v0.y = x1 > 0.f ? x1 : expm1f(x1);
            v1.x = x2 > 0.f ? x2 : expm1f(x2);
            v1.y = x3 > 0.f ? x3 : expm1f(x3);
            *(float2*)&o0[col] = v0;
            *(float2*)&o1[col] = v1;
        }
    }
}

// ---------------------------------------------------------------------------
extern "C" void kernel_launch(void* const* d_in, const int* in_sizes, int n_in,
                              void* d_out, int out_size) {
    const float* h   = (const float*)d_in[0];
    const int*   adj = (const int*)d_in[1];
    const float* W   = (const float*)d_in[2];
    const float* a   = (const float*)d_in[3];
    float*       out = (float*)d_out;

    cudaFuncSetAttribute(wh_tc, cudaFuncAttributeMaxDynamicSharedMemorySize,
                         WG_SMEM_F * 4);
    cudaFuncSetAttribute(attn_mma, cudaFuncAttributeMaxDynamicSharedMemorySize,
                         ATTN_SMEM_F * 4);

    wh_tc<<<(BB * NN) / 64, 256, WG_SMEM_F * 4>>>(h, W);
    f_kernel<<<(BB * NN) / 8, 256>>>(a);
    attn_mma<<<dim3(NN / 128, BB), 512, ATTN_SMEM_F * 4>>>(adj, out);
}

// round 10
// speedup vs baseline: 1.3229x; 1.0080x over previous
#include <cuda_runtime.h>
#include <cuda_fp16.h>
#include <math.h>
#include <stdint.h>

#define BB 8
#define NN 2048
#define FIN 512
#define FOUT 256
#define ALPHA 0.2f

// Scratch (allocation-free rule: __device__ globals)
__device__ float    g_Wh[BB * NN * FOUT];   // [b][j][n] fp32 (tf32-rounded)
__device__ __half   g_WhT[BB * FOUT * NN];  // [b][n][j] fp16 (attn B operand)
__device__ float    g_f1[BB * NN];
__device__ float    g_f2[BB * NN];
__device__ float2   g_e1[BB * NN];          // {exp(f1), exp(ALPHA*f1)}
__device__ float2   g_e2[BB * NN];          // {exp(f2), exp(ALPHA*f2)}
__device__ unsigned g_m2bits[BB * 2];       // per-batch max of e2p / e2n (bits)

// ---------------------------------------------------------------------------
// mma.sync + cp.async helpers (sm_80 baseline — PTX target-safe)
// ---------------------------------------------------------------------------
__device__ __forceinline__ void mma_tf32(float d[4], const uint32_t a[4],
                                         const uint32_t b[2]) {
    asm volatile(
        "mma.sync.aligned.m16n8k8.row.col.f32.tf32.tf32.f32 "
        "{%0,%1,%2,%3}, {%4,%5,%6,%7}, {%8,%9}, {%0,%1,%2,%3};"
        : "+f"(d[0]), "+f"(d[1]), "+f"(d[2]), "+f"(d[3])
        : "r"(a[0]), "r"(a[1]), "r"(a[2]), "r"(a[3]), "r"(b[0]), "r"(b[1]));
}
__device__ __forceinline__ void mma_f16(float d[4], const uint32_t a[4],
                                        uint32_t b0, uint32_t b1) {
    asm volatile(
        "mma.sync.aligned.m16n8k16.row.col.f32.f16.f16.f32 "
        "{%0,%1,%2,%3}, {%4,%5,%6,%7}, {%8,%9}, {%0,%1,%2,%3};"
        : "+f"(d[0]), "+f"(d[1]), "+f"(d[2]), "+f"(d[3])
        : "r"(a[0]), "r"(a[1]), "r"(a[2]), "r"(a[3]), "r"(b0), "r"(b1));
}
__device__ __forceinline__ uint32_t to_tf32(float x) {
    uint32_t r;
    asm("cvt.rna.tf32.f32 %0, %1;" : "=r"(r) : "f"(x));
    return r;
}
__device__ __forceinline__ float tf32f(float x) {
    return __uint_as_float(to_tf32(x));
}
__device__ __forceinline__ void cp_async16(uint32_t dst_smem, const void* src) {
    asm volatile("cp.async.cg.shared.global [%0], [%1], 16;"
                 :: "r"(dst_smem), "l"(src));
}
#define CP_COMMIT() asm volatile("cp.async.commit_group;" ::: "memory")
#define CP_WAIT(n)  asm volatile("cp.async.wait_group %0;" :: "n"(n) : "memory")

// ---------------------------------------------------------------------------
// Kernel 1: Wh = h @ W (tf32 mma.sync). Block 256 thr (2m x 4n warps),
// out tile 64m x 256n. Stores g_Wh (fp32, tf32-rounded) and g_WhT (fp16).
// ---------------------------------------------------------------------------
#define WG_AS 0                        // A_s [64][36]  = 2304 floats
#define WG_BS 2304                     // B_s [32][264] = 8448 floats
#define WG_SMEM_F 10752                // 43008 B

__global__ __launch_bounds__(256, 2) void wh_tc(const float* __restrict__ h,
                                                const float* __restrict__ W) {
    extern __shared__ float sm[];
    float* A_s = sm + WG_AS;
    float* B_s = sm + WG_BS;

    const int tid  = threadIdx.x;
    const int warp = tid >> 5;
    const int lane = tid & 31;
    const int mw   = warp >> 2;
    const int nw   = warp & 3;
    const int g    = lane >> 2;
    const int t    = lane & 3;
    const int row0 = blockIdx.x * 64;

    float acc[2][8][4];
#pragma unroll
    for (int fm = 0; fm < 2; fm++)
#pragma unroll
        for (int fn = 0; fn < 8; fn++)
#pragma unroll
            for (int c = 0; c < 4; c++) acc[fm][fn][c] = 0.f;

    const int r = tid >> 2, q = tid & 3;

    for (int k0 = 0; k0 < FIN; k0 += 32) {
        {
            const float* src = h + (size_t)(row0 + r) * FIN + k0 + q * 8;
            float4 v0 = *(const float4*)src;
            float4 v1 = *(const float4*)(src + 4);
            float* dst = A_s + r * 36 + q * 8;
            dst[0] = tf32f(v0.x); dst[1] = tf32f(v0.y);
            dst[2] = tf32f(v0.z); dst[3] = tf32f(v0.w);
            dst[4] = tf32f(v1.x); dst[5] = tf32f(v1.y);
            dst[6] = tf32f(v1.z); dst[7] = tf32f(v1.w);
        }
#pragma unroll
        for (int p = 0; p < 8; p++) {
            int idx = tid + 256 * p;
            int row = idx >> 6, c4 = idx & 63;
            float4 v = *(const float4*)&W[(size_t)(k0 + row) * FOUT + c4 * 4];
            float4 o;
            o.x = tf32f(v.x); o.y = tf32f(v.y);
            o.z = tf32f(v.z); o.w = tf32f(v.w);
            *(float4*)&B_s[row * 264 + c4 * 4] = o;
        }
        __syncthreads();

#pragma unroll
        for (int fk = 0; fk < 4; fk++) {
            uint32_t A[2][4];
#pragma unroll
            for (int fm = 0; fm < 2; fm++) {
                const float* wa = A_s + (mw * 32 + fm * 16 + g) * 36 + fk * 8 + t;
                A[fm][0] = __float_as_uint(wa[0]);
                A[fm][1] = __float_as_uint(wa[8 * 36]);
                A[fm][2] = __float_as_uint(wa[4]);
                A[fm][3] = __float_as_uint(wa[8 * 36 + 4]);
            }
#pragma unroll
            for (int fn = 0; fn < 8; fn++) {
                uint32_t Bf[2];
                const float* wb = B_s + (fk * 8 + t) * 264 + nw * 64 + fn * 8 + g;
                Bf[0] = __float_as_uint(wb[0]);
                Bf[1] = __float_as_uint(wb[4 * 264]);
                mma_tf32(acc[0][fn], A[0], Bf);
                mma_tf32(acc[1][fn], A[1], Bf);
            }
        }
        __syncthreads();
    }

#pragma unroll
    for (int fm = 0; fm < 2; fm++) {
        int rr = row0 + mw * 32 + fm * 16 + g;
        int bb = rr >> 11;
        int jj = rr & (NN - 1);
        float* o0 = g_Wh + (size_t)rr * FOUT;
        float* o1 = g_Wh + (size_t)(rr + 8) * FOUT;
#pragma unroll
        for (int fn = 0; fn < 8; fn++) {
            int col = nw * 64 + fn * 8 + t * 2;
            // fp32 (tf32-rounded) row-major for f_kernel
            *(float2*)&o0[col] = make_float2(tf32f(acc[fm][fn][0]), tf32f(acc[fm][fn][1]));
            *(float2*)&o1[col] = make_float2(tf32f(acc[fm][fn][2]), tf32f(acc[fm][fn][3]));
            // fp16 transposed [b][n][j] for attn B operand
            size_t base = ((size_t)bb * FOUT + col) * NN + jj;
            g_WhT[base]          = __float2half_rn(acc[fm][fn][0]);
            g_WhT[base + NN]     = __float2half_rn(acc[fm][fn][1]);
            g_WhT[base + 8]      = __float2half_rn(acc[fm][fn][2]);
            g_WhT[base + NN + 8] = __float2half_rn(acc[fm][fn][3]);
        }
    }
}

// ---------------------------------------------------------------------------
// Kernel 2: f1/f2 + exp tables + per-batch max(e2p), max(e2n) via atomicMax
// (idempotent -> deterministic across graph replays; e2 > 0 so bit-max = max)
// ---------------------------------------------------------------------------
__global__ __launch_bounds__(256) void f_kernel(const float* __restrict__ a) {
    int gwarp = (blockIdx.x * blockDim.x + threadIdx.x) >> 5;
    int lane  = threadIdx.x & 31;
    if (gwarp >= BB * NN) return;
    const float* wh = &g_Wh[(size_t)gwarp * FOUT];
    float s1 = 0.f, s2 = 0.f;
#pragma unroll
    for (int u = 0; u < 8; u++) {
        float v = wh[lane + 32 * u];
        s1 += v * a[lane + 32 * u];
        s2 += v * a[FOUT + lane + 32 * u];
    }
#pragma unroll
    for (int off = 16; off; off >>= 1) {
        s1 += __shfl_xor_sync(0xFFFFFFFFu, s1, off);
        s2 += __shfl_xor_sync(0xFFFFFFFFu, s2, off);
    }
    if (lane == 0) {
        g_f1[gwarp] = s1;
        g_f2[gwarp] = s2;
        float e2p = __expf(s2), e2n = __expf(ALPHA * s2);
        g_e1[gwarp] = make_float2(__expf(s1), __expf(ALPHA * s1));
        g_e2[gwarp] = make_float2(e2p, e2n);
        int b = gwarp >> 11;
        atomicMax(&g_m2bits[b * 2 + 0], __float_as_uint(e2p));
        atomicMax(&g_m2bits[b * 2 + 1], __float_as_uint(e2n));
    }
}

// ---------------------------------------------------------------------------
// Kernel 3: fused masked-softmax aggregation, fp16 m16n8k16 mma (fp32 acc).
// Per-row scaling w/s_i (softmax-invariant) keeps fp16 in range [0,1].
// 512 thr, out tile 128 x 256, 64 j-tiles of 32; cp.async double-buffered
// fp16 WhT tiles (raw byte copy). Grid 16x8 = 128 = single wave.
// smem rows: 20 float-slots (= half2) per 32-k row -> conflict-free LDS.32.
// ---------------------------------------------------------------------------
#define SM_WH0  0                      // 256*20 = 5120 floats (half2 slots)
#define SM_WH1  5120
#define SM_W0   10240                  // 128*20 = 2560
#define SM_W1   12800
#define SM_F2   15360                  // 2048
#define SM_E2   17408                  // float2[2048] = 4096
#define SM_F1   21504                  // 128
#define SM_DEN  21632                  // 128
#define ATTN_SMEM_F 21760              // 87040 B

__global__ __launch_bounds__(512, 1) void attn_mma(const int* __restrict__ adj,
                                                   float* __restrict__ out) {
    extern __shared__ float smem[];
    float*  f2s  = smem + SM_F2;
    float2* e2s  = (float2*)(smem + SM_E2);
    float*  f1s  = smem + SM_F1;
    float*  dens = smem + SM_DEN;

    const int tid  = threadIdx.x;
    const int warp = tid >> 5;
    const int lane = tid & 31;
    const int mw   = warp >> 2;
    const int nw   = warp & 3;
    const int g    = lane >> 2;
    const int t    = lane & 3;
    const int b    = blockIdx.y;
    const int i0   = blockIdx.x * 128;

    // Stage f2 / e2 (full row) and f1 (tile)
    {
        const float4* f2g = (const float4*)(g_f2 + b * NN);
        ((float4*)f2s)[tid] = f2g[tid];
        const float4* e2g = (const float4*)(g_e2 + b * NN);
        ((float4*)e2s)[tid]       = e2g[tid];
        ((float4*)e2s)[tid + 512] = e2g[tid + 512];
        if (tid < 128) f1s[tid] = g_f1[b * NN + i0 + tid];
    }

    const int    r    = tid >> 2;   // i-row this thread fills (4 thr/row)
    const int    jq   = tid & 3;    // 8 consecutive j at jq*8
    const int4*  arow = (const int4*)(adj + ((size_t)(b * NN + i0 + r)) * NN + jq * 8);
    const float2 e1   = g_e1[b * NN + i0 + r];
    const __half* whTsrc = g_WhT + (size_t)b * FOUT * NN;

    // per-row scale: s_i = max(e1p*M2p, e1n*M2n)  (tight upper bound on w)
    const float M2p  = __uint_as_float(g_m2bits[b * 2 + 0]);
    const float M2n  = __uint_as_float(g_m2bits[b * 2 + 1]);
    const float sinv = 1.f / fmaxf(e1.x * M2p, e1.y * M2n);
    const float c1p  = e1.x * sinv;
    const float c1n  = e1.y * sinv;

    // cp.async mapping: n-row = tid>>2 (+128p), 16B chunk = tid&3
    const int cpn = tid >> 2;
    const int cpc = tid & 3;
    const uint32_t smem_base = (uint32_t)__cvta_generic_to_shared(smem);

    float acc[2][8][4];
#pragma unroll
    for (int fm = 0; fm < 2; fm++)
#pragma unroll
        for (int fn = 0; fn < 8; fn++)
#pragma unroll
            for (int c = 0; c < 4; c++) acc[fm][fn][c] = 0.f;

    // issue WhT tile 0 copy (rows n: 64B each = 4 chunks)
    {
#pragma unroll
        for (int p = 0; p < 2; p++) {
            int n = cpn + 128 * p;
            const __half* src = whTsrc + (size_t)n * NN + cpc * 8;
            uint32_t dst = smem_base + (SM_WH0 + n * 20 + cpc * 4) * 4;
            cp_async16(dst, src);
        }
        CP_COMMIT();
    }

    __syncthreads();
    const float f1v = f1s[r];
    float den = 0.f;

    int4 avA = arow[0];
    int4 avB = arow[1];

    for (int tt = 0; tt < 64; tt++) {
        const int cur = tt & 1;
        const int j0  = tt * 32;

        // --- w tile fill: exp-free, scaled, fp16-rounded (den matches) ---
        {
            int am[8] = {avA.x, avA.y, avA.z, avA.w, avB.x, avB.y, avB.z, avB.w};
            const float*  f2p = f2s + j0 + jq * 8;
            const float2* e2p = e2s + j0 + jq * 8;
            float wv[8];
#pragma unroll
            for (int u = 0; u < 8; u++) {
                float  e  = f1v + f2p[u];
                float2 e2 = e2p[u];
                float  w  = (e > 0.f) ? c1p * e2.x : c1n * e2.y;
                wv[u] = (am[u] > 0) ? w : 0.f;
            }
            uint32_t pk[4];
#pragma unroll
            for (int i = 0; i < 4; i++) {
                __half2 hp = __floats2half2_rn(wv[2 * i], wv[2 * i + 1]);
                pk[i] = *(uint32_t*)&hp;
                float2 hf = __half22float2(hp);
                den += hf.x + hf.y;
            }
            float* wd = smem + (cur ? SM_W1 : SM_W0) + r * 20 + jq * 4;
            *(float4*)wd = make_float4(__uint_as_float(pk[0]), __uint_as_float(pk[1]),
                                       __uint_as_float(pk[2]), __uint_as_float(pk[3]));
        }
        // --- prefetch next adj + cp.async for WhT tile tt+1 ---
        if (tt < 63) {
            avA = arow[(tt + 1) * 8];
            avB = arow[(tt + 1) * 8 + 1];
#pragma unroll
            for (int p = 0; p < 2; p++) {
                int n = cpn + 128 * p;
                const __half* src = whTsrc + (size_t)n * NN + (tt + 1) * 32 + cpc * 8;
                uint32_t dst = smem_base +
                    ((cur ? SM_WH0 : SM_WH1) + n * 20 + cpc * 4) * 4;
                cp_async16(dst, src);
            }
            CP_COMMIT();
            CP_WAIT(1);
        } else {
            CP_WAIT(0);
        }
        __syncthreads();

        // --- fp16 tensor tile: 2 k-frags of K=16 ---
        const float* w_s = smem + (cur ? SM_W1 : SM_W0);
        const float* B_s = smem + (cur ? SM_WH1 : SM_WH0);
#pragma unroll
        for (int fk = 0; fk < 2; fk++) {
            uint32_t A[2][4];
#pragma unroll
            for (int fm = 0; fm < 2; fm++) {
                const float* wa = w_s + (mw * 32 + fm * 16 + g) * 20 + fk * 8 + t;
                A[fm][0] = __float_as_uint(wa[0]);
                A[fm][1] = __float_as_uint(wa[160]);      // +8 rows
                A[fm][2] = __float_as_uint(wa[4]);
                A[fm][3] = __float_as_uint(wa[164]);
            }
#pragma unroll
            for (int fn = 0; fn < 8; fn++) {
                const float* wb = B_s + (nw * 64 + fn * 8 + g) * 20 + fk * 8 + t;
                uint32_t b0 = __float_as_uint(wb[0]);
                uint32_t b1 = __float_as_uint(wb[4]);
                mma_f16(acc[0][fn], A[0], b0, b1);
                mma_f16(acc[1][fn], A[1], b0, b1);
            }
        }
        __syncthreads();
    }

    // --- denominator: reduce 4 threads per row (scale cancels in ratio) ---
    den += __shfl_xor_sync(0xFFFFFFFFu, den, 1);
    den += __shfl_xor_sync(0xFFFFFFFFu, den, 2);
    if (jq == 0) dens[r] = den;
    __syncthreads();

    // --- epilogue: /den, ELU, store ---
#pragma unroll
    for (int fm = 0; fm < 2; fm++) {
        int row0 = mw * 32 + fm * 16 + g;
        float inv0 = 1.f / dens[row0];
        float inv1 = 1.f / dens[row0 + 8];
        float* o0 = out + ((size_t)(b * NN + i0 + row0)) * FOUT;
        float* o1 = out + ((size_t)(b * NN + i0 + row0 + 8)) * FOUT;
#pragma unroll
        for (int fn = 0; fn < 8; fn++) {
            int col = nw * 64 + fn * 8 + t * 2;
            float x0 = acc[fm][fn][0] * inv0;
            float x1 = acc[fm][fn][1] * inv0;
            float x2 = acc[fm][fn][2] * inv1;
            float x3 = acc[fm][fn][3] * inv1;
            float2 v0, v1;
            v0.x = x0 > 0.f ? x0 : expm1f(x0);
            v0.y = x1 > 0.f ? x1 : expm1f(x1);
            v1.x = x2 > 0.f ? x2 : expm1f(x2);
            v1.y = x3 > 0.f ? x3 : expm1f(x3);
            *(float2*)&o0[col] = v0;
            *(float2*)&o1[col] = v1;
        }
    }
}

// ---------------------------------------------------------------------------
extern "C" void kernel_launch(void* const* d_in, const int* in_sizes, int n_in,
                              void* d_out, int out_size) {
    const float* h   = (const float*)d_in[0];
    const int*   adj = (const int*)d_in[1];
    const float* W   = (const float*)d_in[2];
    const float* a   = (const float*)d_in[3];
    float*       out = (float*)d_out;

    cudaFuncSetAttribute(wh_tc, cudaFuncAttributeMaxDynamicSharedMemorySize,
                         WG_SMEM_F * 4);
    cudaFuncSetAttribute(attn_mma, cudaFuncAttributeMaxDynamicSharedMemorySize,
                         ATTN_SMEM_F * 4);

    wh_tc<<<(BB * NN) / 64, 256, WG_SMEM_F * 4>>>(h, W);
    f_kernel<<<(BB * NN) / 8, 256>>>(a);
    attn_mma<<<dim3(NN / 128, BB), 512, ATTN_SMEM_F * 4>>>(adj, out);
}

// round 11
// speedup vs baseline: 1.4485x; 1.0949x over previous
#include <cuda_runtime.h>
#include <cuda_fp16.h>
#include <math.h>
#include <stdint.h>

#define BB 8
#define NN 2048
#define FIN 512
#define FOUT 256
#define ALPHA 0.2f

// Scratch (allocation-free rule: __device__ globals)
__device__ __half   g_WT[FOUT * FIN];       // [n][k] fp16 (wh B operand)
__device__ __half   g_WhT[BB * FOUT * NN];  // [b][n][j] fp16 (attn B operand)
__device__ float    g_f1[BB * NN];
__device__ float    g_f2[BB * NN];
__device__ float2   g_e1[BB * NN];          // {exp(f1), exp(ALPHA*f1)}
__device__ float2   g_e2[BB * NN];          // {exp(f2), exp(ALPHA*f2)}
__device__ unsigned g_m2bits[BB * 2];       // per-batch max e2p/e2n bits (idempotent)

// ---------------------------------------------------------------------------
// mma.sync + cp.async helpers (sm_80 baseline — PTX target-safe)
// ---------------------------------------------------------------------------
__device__ __forceinline__ void mma_f16(float d[4], const uint32_t a[4],
                                        uint32_t b0, uint32_t b1) {
    asm volatile(
        "mma.sync.aligned.m16n8k16.row.col.f32.f16.f16.f32 "
        "{%0,%1,%2,%3}, {%4,%5,%6,%7}, {%8,%9}, {%0,%1,%2,%3};"
        : "+f"(d[0]), "+f"(d[1]), "+f"(d[2]), "+f"(d[3])
        : "r"(a[0]), "r"(a[1]), "r"(a[2]), "r"(a[3]), "r"(b0), "r"(b1));
}
__device__ __forceinline__ void cp_async16(uint32_t dst_smem, const void* src) {
    asm volatile("cp.async.cg.shared.global [%0], [%1], 16;"
                 :: "r"(dst_smem), "l"(src));
}
#define CP_COMMIT() asm volatile("cp.async.commit_group;" ::: "memory")
#define CP_WAIT(n)  asm volatile("cp.async.wait_group %0;" :: "n"(n) : "memory")
__device__ __forceinline__ uint32_t h2bits(float x, float y) {
    __half2 h = __floats2half2_rn(x, y);
    return *(uint32_t*)&h;
}

// ---------------------------------------------------------------------------
// Kernel 0: W [k][n] fp32 -> g_WT [n][k] fp16 (tiled transpose, tiny)
// ---------------------------------------------------------------------------
__global__ __launch_bounds__(256) void wt_kernel(const float* __restrict__ W) {
    __shared__ float tile[32][33];
    const int k0 = blockIdx.x * 32;
    const int n0 = blockIdx.y * 32;
    const int tx = threadIdx.x & 31, ty = threadIdx.x >> 5;
#pragma unroll
    for (int i = 0; i < 32; i += 8)
        tile[ty + i][tx] = W[(size_t)(k0 + ty + i) * FOUT + n0 + tx];
    __syncthreads();
#pragma unroll
    for (int i = 0; i < 32; i += 8)
        g_WT[(size_t)(n0 + ty + i) * FIN + k0 + tx] = __float2half_rn(tile[tx][ty + i]);
}

// ---------------------------------------------------------------------------
// Kernel 1: Wh = h @ W, fp16 m16n8k16 (fp32 acc). Block 256 thr (2m x 4n),
// out tile 64m x 256n, 16 k-tiles of 32. Epilogue: WhT fp16 store + FUSED
// f1/f2/exp-table computation (f_kernel eliminated; no fp32 Wh in HBM).
// smem rows: 20 float-slots (half2 pairs) -> conflict-free LDS.32 frags.
// ---------------------------------------------------------------------------
#define WH_AS  0                       // 64*20  = 1280 floats (half2 slots)
#define WH_BS  1280                    // 256*20 = 5120
#define WH_SA  6400                    // 512 (a staged)
#define WH_F1P 6912                    // 64*4
#define WH_F2P 7168                    // 64*4
#define WH_SMEM_F 7424                 // 29696 B

__global__ __launch_bounds__(256, 2) void wh_tc(const float* __restrict__ h,
                                                const float* __restrict__ aa) {
    extern __shared__ float sm[];
    float* A_s  = sm + WH_AS;
    float* B_s  = sm + WH_BS;
    float* sA   = sm + WH_SA;
    float* f1p  = sm + WH_F1P;
    float* f2p  = sm + WH_F2P;

    const int tid  = threadIdx.x;
    const int warp = tid >> 5;
    const int lane = tid & 31;
    const int mw   = warp >> 2;    // 0..1
    const int nw   = warp & 3;     // 0..3
    const int g    = lane >> 2;
    const int t    = lane & 3;
    const int row0 = blockIdx.x * 64;

    // stage a (512 floats)
    sA[tid]       = aa[tid];
    sA[tid + 256] = aa[tid + 256];

    float acc[2][8][4];
#pragma unroll
    for (int fm = 0; fm < 2; fm++)
#pragma unroll
        for (int fn = 0; fn < 8; fn++)
#pragma unroll
            for (int c = 0; c < 4; c++) acc[fm][fn][c] = 0.f;

    const int r   = tid >> 2, q = tid & 3;  // A fill: row r, k-chunk q*8
    const int bn  = tid >> 2;               // B fill: n-row (+64p), chunk tid&3
    const int bc  = tid & 3;
    const uint32_t smem_base = (uint32_t)__cvta_generic_to_shared(sm);

    for (int k0 = 0; k0 < FIN; k0 += 32) {
        // --- A tile: h[row0..+64][k0..+32] -> fp16 half2 slots ---
        {
            const float* src = h + (size_t)(row0 + r) * FIN + k0 + q * 8;
            float4 v0 = *(const float4*)src;
            float4 v1 = *(const float4*)(src + 4);
            float* ad = A_s + r * 20 + q * 4;
            ad[0] = __uint_as_float(h2bits(v0.x, v0.y));
            ad[1] = __uint_as_float(h2bits(v0.z, v0.w));
            ad[2] = __uint_as_float(h2bits(v1.x, v1.y));
            ad[3] = __uint_as_float(h2bits(v1.z, v1.w));
        }
        // --- B tile: g_WT[n][k0..+32] raw fp16 copy (cp.async) ---
#pragma unroll
        for (int p = 0; p < 4; p++) {
            int n = bn + 64 * p;
            const __half* src = g_WT + (size_t)n * FIN + k0 + bc * 8;
            uint32_t dst = smem_base + (WH_BS + n * 20 + bc * 4) * 4;
            cp_async16(dst, src);
        }
        CP_COMMIT();
        CP_WAIT(0);
        __syncthreads();

        // --- fp16 tensor tile: 2 k-frags of K=16 (attn-proven scheme) ---
#pragma unroll
        for (int fk = 0; fk < 2; fk++) {
            uint32_t A[2][4];
#pragma unroll
            for (int fm = 0; fm < 2; fm++) {
                const float* wa = A_s + (mw * 32 + fm * 16 + g) * 20 + fk * 8 + t;
                A[fm][0] = __float_as_uint(wa[0]);
                A[fm][1] = __float_as_uint(wa[160]);   // +8 rows
                A[fm][2] = __float_as_uint(wa[4]);
                A[fm][3] = __float_as_uint(wa[164]);
            }
#pragma unroll
            for (int fn = 0; fn < 8; fn++) {
                const float* wb = B_s + (nw * 64 + fn * 8 + g) * 20 + fk * 8 + t;
                uint32_t b0 = __float_as_uint(wb[0]);
                uint32_t b1 = __float_as_uint(wb[4]);
                mma_f16(acc[0][fn], A[0], b0, b1);
                mma_f16(acc[1][fn], A[1], b0, b1);
            }
        }
        __syncthreads();
    }

    // --- epilogue A: WhT fp16 transposed store [b][n][j] ---
#pragma unroll
    for (int fm = 0; fm < 2; fm++) {
        int rr = row0 + mw * 32 + fm * 16 + g;
        int bb = rr >> 11;
        int jj = rr & (NN - 1);
#pragma unroll
        for (int fn = 0; fn < 8; fn++) {
            int col = nw * 64 + fn * 8 + t * 2;
            size_t base = ((size_t)bb * FOUT + col) * NN + jj;
            g_WhT[base]          = __float2half_rn(acc[fm][fn][0]);
            g_WhT[base + NN]     = __float2half_rn(acc[fm][fn][1]);
            g_WhT[base + 8]      = __float2half_rn(acc[fm][fn][2]);
            g_WhT[base + NN + 8] = __float2half_rn(acc[fm][fn][3]);
        }
    }

    // --- epilogue B: fused f1/f2 (deterministic reduction) ---
    {
        float p1[4] = {0.f, 0.f, 0.f, 0.f};   // idx = fm*2 + hi (row +8*hi)
        float p2[4] = {0.f, 0.f, 0.f, 0.f};
#pragma unroll
        for (int fm = 0; fm < 2; fm++)
#pragma unroll
            for (int fn = 0; fn < 8; fn++) {
                int col = nw * 64 + fn * 8 + t * 2;
                float a10 = sA[col], a11 = sA[col + 1];
                float a20 = sA[256 + col], a21 = sA[256 + col + 1];
                p1[fm * 2 + 0] += acc[fm][fn][0] * a10 + acc[fm][fn][1] * a11;
                p1[fm * 2 + 1] += acc[fm][fn][2] * a10 + acc[fm][fn][3] * a11;
                p2[fm * 2 + 0] += acc[fm][fn][0] * a20 + acc[fm][fn][1] * a21;
                p2[fm * 2 + 1] += acc[fm][fn][2] * a20 + acc[fm][fn][3] * a21;
            }
        // quad reduce over t (lanes g*4+t)
#pragma unroll
        for (int off = 1; off <= 2; off <<= 1)
#pragma unroll
            for (int i = 0; i < 4; i++) {
                p1[i] += __shfl_xor_sync(0xFFFFFFFFu, p1[i], off);
                p2[i] += __shfl_xor_sync(0xFFFFFFFFu, p2[i], off);
            }
        if (t == 0) {
#pragma unroll
            for (int fm = 0; fm < 2; fm++)
#pragma unroll
                for (int hi = 0; hi < 2; hi++) {
                    int rowl = mw * 32 + fm * 16 + g + hi * 8;
                    f1p[rowl * 4 + nw] = p1[fm * 2 + hi];
                    f2p[rowl * 4 + nw] = p2[fm * 2 + hi];
                }
        }
    }
    __syncthreads();
    if (tid < 64) {
        float s1 = ((f1p[tid * 4] + f1p[tid * 4 + 1]) + f1p[tid * 4 + 2]) + f1p[tid * 4 + 3];
        float s2 = ((f2p[tid * 4] + f2p[tid * 4 + 1]) + f2p[tid * 4 + 2]) + f2p[tid * 4 + 3];
        int rr = row0 + tid;
        int bb = rr >> 11;
        g_f1[rr] = s1;
        g_f2[rr] = s2;
        float e2p = __expf(s2), e2n = __expf(ALPHA * s2);
        g_e1[rr] = make_float2(__expf(s1), __expf(ALPHA * s1));
        g_e2[rr] = make_float2(e2p, e2n);
        atomicMax(&g_m2bits[bb * 2 + 0], __float_as_uint(e2p));
        atomicMax(&g_m2bits[bb * 2 + 1], __float_as_uint(e2n));
    }
}

// ---------------------------------------------------------------------------
// Kernel 2: fused masked-softmax aggregation, fp16 m16n8k16 (fp32 acc).
// Per-row scaling w/s_i (softmax-invariant) keeps fp16 in [0,1].
// 512 thr, out tile 128 x 256; cp.async double-buffered WhT tiles.
// Grid 16x8 = 128 = single wave.  (AT the legacy-tensor wall.)
// ---------------------------------------------------------------------------
#define SM_WH0  0                      // 256*20 = 5120 floats (half2 slots)
#define SM_WH1  5120
#define SM_W0   10240                  // 128*20 = 2560
#define SM_W1   12800
#define SM_F2   15360                  // 2048
#define SM_E2   17408                  // float2[2048] = 4096
#define SM_F1   21504                  // 128
#define SM_DEN  21632                  // 128
#define ATTN_SMEM_F 21760              // 87040 B

__global__ __launch_bounds__(512, 1) void attn_mma(const int* __restrict__ adj,
                                                   float* __restrict__ out) {
    extern __shared__ float smem[];
    float*  f2s  = smem + SM_F2;
    float2* e2s  = (float2*)(smem + SM_E2);
    float*  f1s  = smem + SM_F1;
    float*  dens = smem + SM_DEN;

    const int tid  = threadIdx.x;
    const int warp = tid >> 5;
    const int lane = tid & 31;
    const int mw   = warp >> 2;
    const int nw   = warp & 3;
    const int g    = lane >> 2;
    const int t    = lane & 3;
    const int b    = blockIdx.y;
    const int i0   = blockIdx.x * 128;

    {
        const float4* f2g = (const float4*)(g_f2 + b * NN);
        ((float4*)f2s)[tid] = f2g[tid];
        const float4* e2g = (const float4*)(g_e2 + b * NN);
        ((float4*)e2s)[tid]       = e2g[tid];
        ((float4*)e2s)[tid + 512] = e2g[tid + 512];
        if (tid < 128) f1s[tid] = g_f1[b * NN + i0 + tid];
    }

    const int    r    = tid >> 2;
    const int    jq   = tid & 3;
    const int4*  arow = (const int4*)(adj + ((size_t)(b * NN + i0 + r)) * NN + jq * 8);
    const float2 e1   = g_e1[b * NN + i0 + r];
    const __half* whTsrc = g_WhT + (size_t)b * FOUT * NN;

    const float M2p  = __uint_as_float(g_m2bits[b * 2 + 0]);
    const float M2n  = __uint_as_float(g_m2bits[b * 2 + 1]);
    const float sinv = 1.f / fmaxf(e1.x * M2p, e1.y * M2n);
    const float c1p  = e1.x * sinv;
    const float c1n  = e1.y * sinv;

    const int cpn = tid >> 2;
    const int cpc = tid & 3;
    const uint32_t smem_base = (uint32_t)__cvta_generic_to_shared(smem);

    float acc[2][8][4];
#pragma unroll
    for (int fm = 0; fm < 2; fm++)
#pragma unroll
        for (int fn = 0; fn < 8; fn++)
#pragma unroll
            for (int c = 0; c < 4; c++) acc[fm][fn][c] = 0.f;

    {
#pragma unroll
        for (int p = 0; p < 2; p++) {
            int n = cpn + 128 * p;
            const __half* src = whTsrc + (size_t)n * NN + cpc * 8;
            uint32_t dst = smem_base + (SM_WH0 + n * 20 + cpc * 4) * 4;
            cp_async16(dst, src);
        }
        CP_COMMIT();
    }

    __syncthreads();
    const float f1v = f1s[r];
    float den = 0.f;

    int4 avA = arow[0];
    int4 avB = arow[1];

    for (int tt = 0; tt < 64; tt++) {
        const int cur = tt & 1;
        const int j0  = tt * 32;

        {
            int am[8] = {avA.x, avA.y, avA.z, avA.w, avB.x, avB.y, avB.z, avB.w};
            const float*  f2p = f2s + j0 + jq * 8;
            const float2* e2p = e2s + j0 + jq * 8;
            float wv[8];
#pragma unroll
            for (int u = 0; u < 8; u++) {
                float  e  = f1v + f2p[u];
                float2 e2 = e2p[u];
                float  w  = (e > 0.f) ? c1p * e2.x : c1n * e2.y;
                wv[u] = (am[u] > 0) ? w : 0.f;
            }
            uint32_t pk[4];
#pragma unroll
            for (int i = 0; i < 4; i++) {
                __half2 hp = __floats2half2_rn(wv[2 * i], wv[2 * i + 1]);
                pk[i] = *(uint32_t*)&hp;
                float2 hf = __half22float2(hp);
                den += hf.x + hf.y;
            }
            float* wd = smem + (cur ? SM_W1 : SM_W0) + r * 20 + jq * 4;
            *(float4*)wd = make_float4(__uint_as_float(pk[0]), __uint_as_float(pk[1]),
                                       __uint_as_float(pk[2]), __uint_as_float(pk[3]));
        }
        if (tt < 63) {
            avA = arow[(tt + 1) * 8];
            avB = arow[(tt + 1) * 8 + 1];
#pragma unroll
            for (int p = 0; p < 2; p++) {
                int n = cpn + 128 * p;
                const __half* src = whTsrc + (size_t)n * NN + (tt + 1) * 32 + cpc * 8;
                uint32_t dst = smem_base +
                    ((cur ? SM_WH0 : SM_WH1) + n * 20 + cpc * 4) * 4;
                cp_async16(dst, src);
            }
            CP_COMMIT();
            CP_WAIT(1);
        } else {
            CP_WAIT(0);
        }
        __syncthreads();

        const float* w_s = smem + (cur ? SM_W1 : SM_W0);
        const float* B_s = smem + (cur ? SM_WH1 : SM_WH0);
#pragma unroll
        for (int fk = 0; fk < 2; fk++) {
            uint32_t A[2][4];
#pragma unroll
            for (int fm = 0; fm < 2; fm++) {
                const float* wa = w_s + (mw * 32 + fm * 16 + g) * 20 + fk * 8 + t;
                A[fm][0] = __float_as_uint(wa[0]);
                A[fm][1] = __float_as_uint(wa[160]);
                A[fm][2] = __float_as_uint(wa[4]);
                A[fm][3] = __float_as_uint(wa[164]);
            }
#pragma unroll
            for (int fn = 0; fn < 8; fn++) {
                const float* wb = B_s + (nw * 64 + fn * 8 + g) * 20 + fk * 8 + t;
                uint32_t b0 = __float_as_uint(wb[0]);
                uint32_t b1 = __float_as_uint(wb[4]);
                mma_f16(acc[0][fn], A[0], b0, b1);
                mma_f16(acc[1][fn], A[1], b0, b1);
            }
        }
        __syncthreads();
    }

    den += __shfl_xor_sync(0xFFFFFFFFu, den, 1);
    den += __shfl_xor_sync(0xFFFFFFFFu, den, 2);
    if (jq == 0) dens[r] = den;
    __syncthreads();

#pragma unroll
    for (int fm = 0; fm < 2; fm++) {
        int row0 = mw * 32 + fm * 16 + g;
        float inv0 = 1.f / dens[row0];
        float inv1 = 1.f / dens[row0 + 8];
        float* o0 = out + ((size_t)(b * NN + i0 + row0)) * FOUT;
        float* o1 = out + ((size_t)(b * NN + i0 + row0 + 8)) * FOUT;
#pragma unroll
        for (int fn = 0; fn < 8; fn++) {
            int col = nw * 64 + fn * 8 + t * 2;
            float x0 = acc[fm][fn][0] * inv0;
            float x1 = acc[fm][fn][1] * inv0;
            float x2 = acc[fm][fn][2] * inv1;
            float x3 = acc[fm][fn][3] * inv1;
            float2 v0, v1;
            v0.x = x0 > 0.f ? x0 : expm1f(x0);
            v0.y = x1 > 0.f ? x1 : expm1f(x1);
            v1.x = x2 > 0.f ? x2 : expm1f(x2);
            v1.y = x3 > 0.f ? x3 : expm1f(x3);
            *(float2*)&o0[col] = v0;
            *(float2*)&o1[col] = v1;
        }
    }
}

// ---------------------------------------------------------------------------
extern "C" void kernel_launch(void* const* d_in, const int* in_sizes, int n_in,
                              void* d_out, int out_size) {
    const float* h   = (const float*)d_in[0];
    const int*   adj = (const int*)d_in[1];
    const float* W   = (const float*)d_in[2];
    const float* a   = (const float*)d_in[3];
    float*       out = (float*)d_out;

    cudaFuncSetAttribute(wh_tc, cudaFuncAttributeMaxDynamicSharedMemorySize,
                         WH_SMEM_F * 4);
    cudaFuncSetAttribute(attn_mma, cudaFuncAttributeMaxDynamicSharedMemorySize,
                         ATTN_SMEM_F * 4);

    wt_kernel<<<dim3(FIN / 32, FOUT / 32), 256>>>(W);
    wh_tc<<<(BB * NN) / 64, 256, WH_SMEM_F * 4>>>(h, a);
    attn_mma<<<dim3(NN / 128, BB), 512, ATTN_SMEM_F * 4>>>(adj, out);
}